// round 12
// baseline (speedup 1.0000x reference)
#include <cuda_runtime.h>
#include <cuda_bf16.h>
#include <cstdint>

#define NN  100000
#define NNP 100032          // 1563 tiles of 64 rows
#define NE  1600000
#define NGR 512
#define FIN 7
#define HID 128
#define HB  6250            // edge-hist blocks
#define SB  98              // scan blocks (98*1024 >= NN)

// ---------------- scratch (static device globals; zero-initialized) ----------------
__device__ __align__(16) unsigned d_Hh[(size_t)NNP * 64];   // GEMM output, bf16 [row][128]
__device__ __align__(16) float d_t [(size_t)NN * 2];
// A hi/lo bf16 tiles: [row][256B] XOR-granule swizzled (pad rows stay zero)
__device__ __align__(16) unsigned char d_Ahi[(size_t)NNP * 256];
__device__ __align__(16) unsigned char d_Alo[(size_t)NNP * 256];
// W hi/lo bf16, transposed [n][k], 256B rows, swizzled (32 KB each)
__device__ __align__(16) unsigned char d_B2hi[32768], d_B2lo[32768];
__device__ __align__(16) unsigned char d_B3hi[32768], d_B3lo[32768];
__device__ float d_dinv[NN];
__device__ int   d_counts[NN];
__device__ int   d_cursor[NN];
__device__ int   d_off[NN + 1];
__device__ int   d_bsum[SB];
__device__ int   d_csrc[NE];
__device__ float d_pool2[NGR * 2];
__device__ int   d_gcnt[NGR];
__device__ float d_W4p[HID * 2];
__device__ float d_b4p[2];
__device__ int   d_is64_ei;
__device__ int   d_is64_batch;

__device__ __forceinline__ int load_idx(const void* p, int is64, long long i) {
    return is64 ? (int)((const long long*)p)[i] : ((const int*)p)[i];
}

// ---------------- bf16 helpers ----------------
__device__ __forceinline__ unsigned short bfh(float v) {
    return __bfloat16_as_ushort(__float2bfloat16(v));
}
__device__ __forceinline__ float bf2f(unsigned short u) {
    return __bfloat162float(__ushort_as_bfloat16(u));
}
__device__ __forceinline__ unsigned packbf2(float lo, float hi) {
    __nv_bfloat162 p = __float22bfloat162_rn(make_float2(lo, hi));
    return *reinterpret_cast<unsigned*>(&p);
}
__device__ __forceinline__ float4 bf4(uint2 r) {
    __nv_bfloat162 a = *reinterpret_cast<__nv_bfloat162*>(&r.x);
    __nv_bfloat162 b = *reinterpret_cast<__nv_bfloat162*>(&r.y);
    float2 fa = __bfloat1622float2(a);
    float2 fb = __bfloat1622float2(b);
    return make_float4(fa.x, fa.y, fb.x, fb.y);
}

// swizzled byte offset within a [rows][256B] bf16 image: 16B granules XORed by row&7
__device__ __forceinline__ unsigned sw_off(int row, int kb) {
    return (unsigned)(row * 256) + ((((unsigned)kb >> 4) ^ ((unsigned)row & 7u)) << 4)
         + ((unsigned)kb & 15u);
}

// ---------------- mma.sync m16n8k16 bf16 ----------------
__device__ __forceinline__ void mma_bf16(float c[4], const unsigned a[4], const unsigned b[2]) {
    asm volatile(
        "mma.sync.aligned.m16n8k16.row.col.f32.bf16.bf16.f32 "
        "{%0,%1,%2,%3}, {%4,%5,%6,%7}, {%8,%9}, {%0,%1,%2,%3};"
        : "+f"(c[0]), "+f"(c[1]), "+f"(c[2]), "+f"(c[3])
        : "r"(a[0]), "r"(a[1]), "r"(a[2]), "r"(a[3]), "r"(b[0]), "r"(b[1]));
}

// ---------------- setup: zero + dtype probe + wconv(W2,W3) + fold ----------------
__global__ void k_setup(const void* ei, const void* batch,
                        const float* __restrict__ W2, const float* __restrict__ W3,
                        const float* __restrict__ W4, const float* __restrict__ b4,
                        const float* __restrict__ Wlin, const float* __restrict__ blin) {
    int bid = blockIdx.x;
    if (bid < 512) {                       // zeroing
        int i = bid * 256 + threadIdx.x;
        int stride = 512 * 256;
        for (int t = i; t < NN; t += stride) { d_counts[t] = 0; d_cursor[t] = 0; }
        for (int t = i; t < NGR * 2; t += stride) d_pool2[t] = 0.f;
        for (int t = i; t < NGR; t += stride) d_gcnt[t] = 0;
    } else if (bid == 512) {               // dtype probe
        if (threadIdx.x < 32) {
            const int* w1 = (const int*)ei;
            const int* w2 = (const int*)batch;
            int lane = threadIdx.x;
            int nz1 = 0, nz2 = 0;
            for (int i = 2 * lane + 1; i < 4096; i += 64) { nz1 |= w1[i]; nz2 |= w2[i]; }
            nz1 = __reduce_or_sync(0xffffffffu, nz1);
            nz2 = __reduce_or_sync(0xffffffffu, nz2);
            if (lane == 0) { d_is64_ei = (nz1 == 0); d_is64_batch = (nz2 == 0); }
        }
    } else if (bid < 577) {                // wconv: split-bf16 transposed W tiles
        int idx64 = bid - 513;             // 0..63
        int sel = idx64 >> 5;
        const float* W = sel ? W3 : W2;
        int idx = (idx64 & 31) * 256 + threadIdx.x;   // < 8192
        int n = idx >> 6;
        int k = (idx & 63) * 2;
        float v0 = W[k * HID + n];
        float v1 = W[(k + 1) * HID + n];
        unsigned short h0 = bfh(v0), h1 = bfh(v1);
        unsigned short l0 = bfh(v0 - bf2f(h0)), l1 = bfh(v1 - bf2f(h1));
        unsigned off = sw_off(n, k * 2);
        unsigned char* bh = sel ? d_B3hi : d_B2hi;
        unsigned char* bl = sel ? d_B3lo : d_B2lo;
        *(unsigned*)(bh + off) = (unsigned)h0 | ((unsigned)h1 << 16);
        *(unsigned*)(bl + off) = (unsigned)l0 | ((unsigned)l1 << 16);
    } else {                               // fold: W4p = W4 @ Wlin, b4p
        int j = threadIdx.x;
        if (j >= HID) return;
        float s0 = 0.f, s1 = 0.f;
#pragma unroll 8
        for (int k = 0; k < HID; k++) {
            float w = W4[j * HID + k];
            s0 += w * Wlin[k * 2 + 0];
            s1 += w * Wlin[k * 2 + 1];
        }
        d_W4p[j * 2 + 0] = s0;
        d_W4p[j * 2 + 1] = s1;
        if (j < 2) {
            float s = 0.f;
            for (int k = 0; k < HID; k++) s += b4[k] * Wlin[k * 2 + j];
            d_b4p[j] = s + blin[j];
        }
    }
}

// ---------------- degree histogram + nodes-per-graph histogram ----------------
__global__ void __launch_bounds__(256) k_hist(const void* __restrict__ ei,
                                              const void* __restrict__ batch) {
    __shared__ int sh[NGR];
    if (blockIdx.x < HB) {
        int e = blockIdx.x * 256 + threadIdx.x;
        if (e >= NE) return;
        unsigned d = (unsigned)load_idx(ei, d_is64_ei, (long long)NE + e);
        if (d < NN) atomicAdd(&d_counts[d], 1);
    } else {
        for (int t = threadIdx.x; t < NGR; t += 256) sh[t] = 0;
        __syncthreads();
        int is64 = d_is64_batch;
        for (int i = (blockIdx.x - HB) * 256 + threadIdx.x; i < NN; i += 64 * 256) {
            unsigned g = (unsigned)load_idx(batch, is64, i);
            if (g < NGR) atomicAdd(&sh[g], 1);
        }
        __syncthreads();
        for (int t = threadIdx.x; t < NGR; t += 256)
            if (sh[t]) atomicAdd(&d_gcnt[t], sh[t]);
    }
}

// ---------------- scan phase 1: per-block reduce (+dinv) ----------------
__global__ void __launch_bounds__(1024) k_scan1() {
    __shared__ int ws[32];
    int i = blockIdx.x * 1024 + threadIdx.x;
    int v = 0;
    if (i < NN) {
        v = d_counts[i];
        d_dinv[i] = rsqrtf((float)v + 1.0f);
    }
    int s = v;
#pragma unroll
    for (int o = 16; o > 0; o >>= 1) s += __shfl_down_sync(0xffffffffu, s, o);
    if ((threadIdx.x & 31) == 0) ws[threadIdx.x >> 5] = s;
    __syncthreads();
    if (threadIdx.x < 32) {
        int t = ws[threadIdx.x];
#pragma unroll
        for (int o = 16; o > 0; o >>= 1) t += __shfl_down_sync(0xffffffffu, t, o);
        if (threadIdx.x == 0) d_bsum[blockIdx.x] = t;
    }
}

// ---------------- scan phases 2+3: base from partials + block scan -> d_off -------
__global__ void __launch_bounds__(1024) k_scan23() {
    __shared__ int sc[32];
    __shared__ int wsum[32];
    __shared__ int sbase;
    int t = threadIdx.x;
    if (t == 0) {
        int base = 0, tot = 0;
        for (int b = 0; b < SB; b++) {
            int v = d_bsum[b];
            if (b < (int)blockIdx.x) base += v;
            tot += v;
        }
        sbase = base;
        if (blockIdx.x == 0) d_off[NN] = tot;
    }
    int i = blockIdx.x * 1024 + t;
    int v = (i < NN) ? d_counts[i] : 0;
    int incl = v;
#pragma unroll
    for (int o = 1; o < 32; o <<= 1) {
        int n = __shfl_up_sync(0xffffffffu, incl, o);
        if ((t & 31) >= o) incl += n;
    }
    if ((t & 31) == 31) wsum[t >> 5] = incl;
    __syncthreads();
    if (t < 32) {
        int w = wsum[t];
#pragma unroll
        for (int o = 1; o < 32; o <<= 1) {
            int n = __shfl_up_sync(0xffffffffu, w, o);
            if (t >= o) w += n;
        }
        sc[t] = w;
    }
    __syncthreads();
    int warp = t >> 5;
    int base = sbase + (warp ? sc[warp - 1] : 0);
    if (i < NN) d_off[i] = base + incl - v;
}

// ---------------- scatter edges into CSR (by dst); norm factored out ----------------
__global__ void k_scatter(const void* __restrict__ ei) {
    int e = blockIdx.x * blockDim.x + threadIdx.x;
    if (e >= NE) return;
    int is64 = d_is64_ei;
    unsigned s = (unsigned)load_idx(ei, is64, e);
    unsigned d = (unsigned)load_idx(ei, is64, (long long)NE + e);
    if (s >= NN || d >= NN) return;
    int pos = d_off[d] + atomicAdd(&d_cursor[d], 1);
    d_csrc[pos] = (int)s;
}

// ---------------- fused: (ÂX)W1 + b1, relu -> split-bf16 A tiles ----------------
__global__ void __launch_bounds__(128) k_aggx7(const float* __restrict__ x,
                                               const float* __restrict__ W1,
                                               const float* __restrict__ b1) {
    __shared__ float sax[16][8];
    __shared__ float sW[FIN * HID];
    __shared__ float sb[HID];
    const int tid = threadIdx.x;
    for (int t = tid; t < FIN * HID; t += 128) sW[t] = W1[t];
    sb[tid] = b1[tid];

    const int sub = tid & 7;
    const int local = tid >> 3;
    const int i = blockIdx.x * 16 + local;          // always < NN
    const int col = (sub < 7) ? sub : 6;
    const float di = d_dinv[i];
    float acc = di * x[i * 7 + col];
    int e = d_off[i];
    const int e1 = d_off[i + 1];
    for (; e + 2 <= e1; e += 2) {
        int s0 = d_csrc[e], s1 = d_csrc[e + 1];
        float w0 = d_dinv[s0], w1 = d_dinv[s1];
        acc += w0 * x[s0 * 7 + col] + w1 * x[s1 * 7 + col];
    }
    if (e < e1) { int s = d_csrc[e]; acc += d_dinv[s] * x[s * 7 + col]; }
    sax[local][sub] = acc * di;
    __syncthreads();

#pragma unroll
    for (int j = 0; j < 8; j++) {
        int task = tid + j * 128;
        int node = task >> 6;
        int jp = (task & 63) * 2;
        float a0 = sb[jp], a1 = sb[jp + 1];
#pragma unroll
        for (int k = 0; k < FIN; k++) {
            float a = sax[node][k];
            a0 += a * sW[k * HID + jp];
            a1 += a * sW[k * HID + jp + 1];
        }
        a0 = fmaxf(a0, 0.f); a1 = fmaxf(a1, 0.f);
        unsigned short h0 = bfh(a0), h1 = bfh(a1);
        unsigned short l0 = bfh(a0 - bf2f(h0)), l1 = bfh(a1 - bf2f(h1));
        int row = blockIdx.x * 16 + node;
        unsigned off = sw_off(row, jp * 2);
        *(unsigned*)(d_Ahi + off) = (unsigned)h0 | ((unsigned)h1 << 16);
        *(unsigned*)(d_Alo + off) = (unsigned)l0 | ((unsigned)l1 << 16);
    }
}

// ---------------- 128x128 GEMM via mma.sync bf16x3: Atiles @ W -> d_Hh (bf16) ------
__global__ void __launch_bounds__(256) k_gemm128(int sel) {
    extern __shared__ __align__(16) unsigned char smem[];
    unsigned char* As_hi = smem;            // 64*256 = 16 KB
    unsigned char* As_lo = smem + 16384;
    unsigned char* Bs_hi = smem + 32768;    // 128*256 = 32 KB
    unsigned char* Bs_lo = smem + 65536;
    const int tid = threadIdx.x;

    {
        const uint4* ah = (const uint4*)d_Ahi + (size_t)blockIdx.x * 1024;
        const uint4* al = (const uint4*)d_Alo + (size_t)blockIdx.x * 1024;
        const uint4* bh = (const uint4*)(sel ? d_B3hi : d_B2hi);
        const uint4* bl = (const uint4*)(sel ? d_B3lo : d_B2lo);
        uint4* sah = (uint4*)As_hi;
        uint4* sal = (uint4*)As_lo;
        uint4* sbh = (uint4*)Bs_hi;
        uint4* sbl = (uint4*)Bs_lo;
#pragma unroll
        for (int i = 0; i < 4; i++) sah[tid + i * 256] = ah[tid + i * 256];
#pragma unroll
        for (int i = 0; i < 4; i++) sal[tid + i * 256] = al[tid + i * 256];
#pragma unroll
        for (int i = 0; i < 8; i++) sbh[tid + i * 256] = bh[tid + i * 256];
#pragma unroll
        for (int i = 0; i < 8; i++) sbl[tid + i * 256] = bl[tid + i * 256];
    }
    __syncthreads();

    const int w = tid >> 5, lane = tid & 31;
    const int wm = (w & 1) * 32;
    const int wn = (w >> 1) * 32;
    const int lr = lane >> 2;
    const int kq = (lane & 3) * 4;

    float c[2][4][4] = {};

#pragma unroll
    for (int ks = 0; ks < 8; ks++) {
        const int kb0 = ks * 32;
        unsigned ah[2][4], al[2][4], bh[4][2], bl[4][2];
#pragma unroll
        for (int mt = 0; mt < 2; mt++) {
            int r = wm + mt * 16 + lr;
            ah[mt][0] = *(const unsigned*)(As_hi + sw_off(r,     kb0 + kq));
            ah[mt][1] = *(const unsigned*)(As_hi + sw_off(r + 8, kb0 + kq));
            ah[mt][2] = *(const unsigned*)(As_hi + sw_off(r,     kb0 + 16 + kq));
            ah[mt][3] = *(const unsigned*)(As_hi + sw_off(r + 8, kb0 + 16 + kq));
            al[mt][0] = *(const unsigned*)(As_lo + sw_off(r,     kb0 + kq));
            al[mt][1] = *(const unsigned*)(As_lo + sw_off(r + 8, kb0 + kq));
            al[mt][2] = *(const unsigned*)(As_lo + sw_off(r,     kb0 + 16 + kq));
            al[mt][3] = *(const unsigned*)(As_lo + sw_off(r + 8, kb0 + 16 + kq));
        }
#pragma unroll
        for (int nt = 0; nt < 4; nt++) {
            int n = wn + nt * 8 + lr;
            bh[nt][0] = *(const unsigned*)(Bs_hi + sw_off(n, kb0 + kq));
            bh[nt][1] = *(const unsigned*)(Bs_hi + sw_off(n, kb0 + 16 + kq));
            bl[nt][0] = *(const unsigned*)(Bs_lo + sw_off(n, kb0 + kq));
            bl[nt][1] = *(const unsigned*)(Bs_lo + sw_off(n, kb0 + 16 + kq));
        }
#pragma unroll
        for (int mt = 0; mt < 2; mt++)
#pragma unroll
            for (int nt = 0; nt < 4; nt++) {
                mma_bf16(c[mt][nt], ah[mt], bh[nt]);
                mma_bf16(c[mt][nt], ah[mt], bl[nt]);
                mma_bf16(c[mt][nt], al[mt], bh[nt]);
            }
    }

    // epilogue: bf16 pairs -> d_Hh (row-major [row][64 uint])
    const int node0 = blockIdx.x * 64;
#pragma unroll
    for (int mt = 0; mt < 2; mt++) {
#pragma unroll
        for (int nt = 0; nt < 4; nt++) {
            int row = node0 + wm + mt * 16 + lr;
            int cu = (wn + nt * 8 + (lane & 3) * 2) >> 1;   // uint index (col even)
            d_Hh[(size_t)row * 64 + cu]       = packbf2(c[mt][nt][0], c[mt][nt][1]);
            d_Hh[(size_t)(row + 8) * 64 + cu] = packbf2(c[mt][nt][2], c[mt][nt][3]);
        }
    }
}

// ---------------- aggregation core (warp/node, 4 bf16/lane, unroll 8) --------------
// returns dinv_i * (dinv_i*v_i + sum dinv_s*v_s) + b
__device__ __forceinline__ float4 agg_core(int i, int lane, const float* __restrict__ b) {
    const uint2* hw2 = (const uint2*)d_Hh;
    const float di = d_dinv[i];
    float4 acc = bf4(hw2[(size_t)i * 32 + lane]);
    acc.x *= di; acc.y *= di; acc.z *= di; acc.w *= di;
    int e = d_off[i];
    const int e1 = d_off[i + 1];
    for (; e + 8 <= e1; e += 8) {
        int s[8]; float ds[8]; uint2 r[8];
#pragma unroll
        for (int j = 0; j < 8; j++) s[j] = d_csrc[e + j];
#pragma unroll
        for (int j = 0; j < 8; j++) ds[j] = d_dinv[s[j]];
#pragma unroll
        for (int j = 0; j < 8; j++) r[j] = hw2[(size_t)s[j] * 32 + lane];
#pragma unroll
        for (int j = 0; j < 8; j++) {
            float4 v = bf4(r[j]);
            acc.x += ds[j] * v.x; acc.y += ds[j] * v.y;
            acc.z += ds[j] * v.z; acc.w += ds[j] * v.w;
        }
    }
    for (; e < e1; e++) {
        int s = d_csrc[e];
        float ds = d_dinv[s];
        float4 v = bf4(hw2[(size_t)s * 32 + lane]);
        acc.x += ds * v.x; acc.y += ds * v.y; acc.z += ds * v.z; acc.w += ds * v.w;
    }
    float4 bv = ((const float4*)b)[lane];
    acc.x = acc.x * di + bv.x; acc.y = acc.y * di + bv.y;
    acc.z = acc.z * di + bv.z; acc.w = acc.w * di + bv.w;
    return acc;
}

// layer-2 aggregation: emit relu'd split-bf16 A tiles for the next GEMM
__global__ void __launch_bounds__(128) k_aggT(const float* __restrict__ b) {
    const int lane = threadIdx.x & 31;
    const int i = blockIdx.x * 4 + (threadIdx.x >> 5);
    if (i >= NN) return;
    float4 acc = agg_core(i, lane, b);
    acc.x = fmaxf(acc.x, 0.f); acc.y = fmaxf(acc.y, 0.f);
    acc.z = fmaxf(acc.z, 0.f); acc.w = fmaxf(acc.w, 0.f);
    unsigned short h0 = bfh(acc.x), h1 = bfh(acc.y), h2 = bfh(acc.z), h3 = bfh(acc.w);
    unsigned short l0 = bfh(acc.x - bf2f(h0)), l1 = bfh(acc.y - bf2f(h1));
    unsigned short l2 = bfh(acc.z - bf2f(h2)), l3 = bfh(acc.w - bf2f(h3));
    unsigned long long ph = (unsigned long long)((unsigned)h0 | ((unsigned)h1 << 16))
                          | ((unsigned long long)((unsigned)h2 | ((unsigned)h3 << 16)) << 32);
    unsigned long long pl = (unsigned long long)((unsigned)l0 | ((unsigned)l1 << 16))
                          | ((unsigned long long)((unsigned)l2 | ((unsigned)l3 << 16)) << 32);
    unsigned off = sw_off(i, lane * 8);
    *(unsigned long long*)(d_Ahi + off) = ph;
    *(unsigned long long*)(d_Alo + off) = pl;
}

// layer-3 aggregation fused with folded layer-4 GEMV: d_t = relu(agg) @ W4p
__global__ void __launch_bounds__(128) k_aggG(const float* __restrict__ b) {
    __shared__ float sw[HID * 2];
    const int tid = threadIdx.x;
    sw[tid] = d_W4p[tid];
    sw[tid + 128] = d_W4p[tid + 128];
    __syncthreads();

    const int lane = tid & 31;
    const int i = blockIdx.x * 4 + (tid >> 5);
    if (i >= NN) return;
    float4 a = agg_core(i, lane, b);
    a.x = fmaxf(a.x, 0.f); a.y = fmaxf(a.y, 0.f);
    a.z = fmaxf(a.z, 0.f); a.w = fmaxf(a.w, 0.f);
    const int j0 = lane * 4;
    float s0 = a.x * sw[(j0+0)*2]   + a.y * sw[(j0+1)*2]   + a.z * sw[(j0+2)*2]   + a.w * sw[(j0+3)*2];
    float s1 = a.x * sw[(j0+0)*2+1] + a.y * sw[(j0+1)*2+1] + a.z * sw[(j0+2)*2+1] + a.w * sw[(j0+3)*2+1];
#pragma unroll
    for (int o = 16; o > 0; o >>= 1) {
        s0 += __shfl_down_sync(0xffffffffu, s0, o);
        s1 += __shfl_down_sync(0xffffffffu, s1, o);
    }
    if (lane == 0) {
        d_t[i * 2 + 0] = s0;
        d_t[i * 2 + 1] = s1;
    }
}

// ---------------- 2-wide aggregation fused with pooling (warp-agg atomics) ---------
__global__ void k_agg2pool(const void* __restrict__ batch) {
    int i = blockIdx.x * blockDim.x + threadIdx.x;
    bool valid = i < NN;
    float a0 = 0.f, a1 = 0.f;
    unsigned g = 0xffffffffu;
    if (valid) {
        const float2* t2 = (const float2*)d_t;
        const float di = d_dinv[i];
        float2 ti = t2[i];
        a0 = di * ti.x; a1 = di * ti.y;
        const int e1 = d_off[i + 1];
        for (int e = d_off[i]; e < e1; e++) {
            int s = d_csrc[e];
            float ds = d_dinv[s];
            float2 ts = t2[s];
            a0 += ds * ts.x; a1 += ds * ts.y;
        }
        a0 *= di; a1 *= di;
        g = (unsigned)load_idx(batch, d_is64_batch, i);
    }
    unsigned g0 = __shfl_sync(0xffffffffu, g, 0);
    bool uni = __all_sync(0xffffffffu, g == g0);
    if (uni && g0 < NGR) {
#pragma unroll
        for (int o = 16; o > 0; o >>= 1) {
            a0 += __shfl_down_sync(0xffffffffu, a0, o);
            a1 += __shfl_down_sync(0xffffffffu, a1, o);
        }
        if ((threadIdx.x & 31) == 0) {
            atomicAdd(&d_pool2[g0 * 2 + 0], a0);
            atomicAdd(&d_pool2[g0 * 2 + 1], a1);
        }
    } else if (valid && g < NGR) {
        atomicAdd(&d_pool2[g * 2 + 0], a0);
        atomicAdd(&d_pool2[g * 2 + 1], a1);
    }
}

// ---------------- output: mean + folded bias ----------------
__global__ void k_out(float* __restrict__ out) {
    int idx = blockIdx.x * blockDim.x + threadIdx.x;
    if (idx >= NGR * 2) return;
    int g = idx >> 1, c = idx & 1;
    float cnt = fmaxf((float)d_gcnt[g], 1.0f);
    out[idx] = d_pool2[g * 2 + c] / cnt + d_b4p[c];
}

// ---------------- launch ----------------
extern "C" void kernel_launch(void* const* d_in, const int* in_sizes, int n_in,
                              void* d_out, int out_size) {
    // Resolve inputs by element count — robust to metadata ordering.
    int ix = 0, iei = 1, ibatch = 2, iW1 = 3, iWlin = 11, iblin = 12;
    int iW[3] = {5, 7, 9};
    int ib[4] = {4, 6, 8, 10};
    {
        int nW = 0, nb = 0;
        int fx = -1, fei = -1, fb = -1, fW1 = -1, fWl = -1, fbl = -1;
        int fW[3] = {-1, -1, -1}, fbias[4] = {-1, -1, -1, -1};
        for (int i = 0; i < n_in; i++) {
            switch (in_sizes[i]) {
                case 700000:  fx  = i; break;
                case 3200000: fei = i; break;
                case 100000:  fb  = i; break;
                case 896:     fW1 = i; break;
                case 16384:   if (nW < 3) fW[nW++] = i; break;
                case 128:     if (nb < 4) fbias[nb++] = i; break;
                case 256:     fWl = i; break;
                case 2:       fbl = i; break;
                default: break;
            }
        }
        if (fx >= 0 && fei >= 0 && fb >= 0 && fW1 >= 0 && fWl >= 0 && fbl >= 0 &&
            nW == 3 && nb == 4) {
            ix = fx; iei = fei; ibatch = fb; iW1 = fW1; iWlin = fWl; iblin = fbl;
            iW[0] = fW[0]; iW[1] = fW[1]; iW[2] = fW[2];
            ib[0] = fbias[0]; ib[1] = fbias[1]; ib[2] = fbias[2]; ib[3] = fbias[3];
        }
    }

    const float* x     = (const float*)d_in[ix];
    const void*  ei    = d_in[iei];
    const void*  batch = d_in[ibatch];
    float* out = (float*)d_out;

    const int GEMM_SMEM = 96 * 1024;
    cudaFuncSetAttribute(k_gemm128, cudaFuncAttributeMaxDynamicSharedMemorySize, GEMM_SMEM);

    k_setup<<<578, 256>>>(ei, batch,
                          (const float*)d_in[iW[0]], (const float*)d_in[iW[1]],
                          (const float*)d_in[iW[2]], (const float*)d_in[ib[3]],
                          (const float*)d_in[iWlin], (const float*)d_in[iblin]);
    k_hist<<<HB + 64, 256>>>(ei, batch);
    k_scan1<<<SB, 1024>>>();
    k_scan23<<<SB, 1024>>>();
    k_scatter<<<(NE + 255) / 256, 256>>>(ei);

    // layer 1: fused (ÂX)W1 + b1, relu -> split tiles
    k_aggx7<<<NN / 16, 128>>>(x, (const float*)d_in[iW1], (const float*)d_in[ib[0]]);
    // layer 2: MMA + aggregation (emit tiles for layer 3)
    k_gemm128<<<NNP / 64, 256, GEMM_SMEM>>>(0);
    k_aggT<<<NN / 4, 128>>>((const float*)d_in[ib[1]]);
    // layer 3: MMA + aggregation fused with folded layer-4 GEMV
    k_gemm128<<<NNP / 64, 256, GEMM_SMEM>>>(1);
    k_aggG<<<NN / 4, 128>>>((const float*)d_in[ib[2]]);
    // pooled 2-wide aggregation + head
    k_agg2pool<<<(NN + 255) / 256, 256>>>(batch);
    k_out<<<(NGR * 2 + 255) / 256, 256>>>(out);
}

// round 13
// speedup vs baseline: 1.4244x; 1.4244x over previous
#include <cuda_runtime.h>
#include <cuda_bf16.h>
#include <cstdint>

#define NN  100000
#define NNP 100096          // 391 CTAs x 256 rows (pad rows stay zero)
#define NE  1600000
#define NGR 512
#define FIN 7
#define HID 128
#define HB  6250            // edge-hist blocks
#define SB  98              // scan blocks (98*1024 >= NN)

// ---------------- scratch (static device globals; zero-initialized) ----------------
__device__ __align__(16) float d_hw[(size_t)NNP * HID];
__device__ __align__(16) float d_t [(size_t)NN * 2];
// A hi/lo bf16 tiles: [row][256B] XOR-granule swizzled (pad rows stay zero)
__device__ __align__(16) unsigned char d_Ahi[(size_t)NNP * 256];
__device__ __align__(16) unsigned char d_Alo[(size_t)NNP * 256];
// W hi/lo bf16, transposed [n][k], 256B rows, swizzled (32 KB each)
__device__ __align__(16) unsigned char d_B2hi[32768], d_B2lo[32768];
__device__ __align__(16) unsigned char d_B3hi[32768], d_B3lo[32768];
__device__ float d_dinv[NN];
__device__ int   d_counts[NN];
__device__ int   d_cursor[NN];
__device__ int   d_off[NN + 1];
__device__ int   d_bsum[SB];
__device__ int   d_csrc[NE];
__device__ float d_pool2[NGR * 2];
__device__ int   d_gcnt[NGR];
__device__ float d_W4p[HID * 2];
__device__ float d_b4p[2];
__device__ int   d_is64_ei;
__device__ int   d_is64_batch;

__device__ __forceinline__ int load_idx(const void* p, int is64, long long i) {
    return is64 ? (int)((const long long*)p)[i] : ((const int*)p)[i];
}

// ---------------- bf16 split helpers ----------------
__device__ __forceinline__ unsigned short bfh(float v) {
    return __bfloat16_as_ushort(__float2bfloat16(v));
}
__device__ __forceinline__ float bf2f(unsigned short u) {
    return __bfloat162float(__ushort_as_bfloat16(u));
}

// swizzled byte offset within a [rows][256B] bf16 image: 16B granules XORed by row&7
__device__ __forceinline__ unsigned sw_off(int row, int kb) {
    return (unsigned)(row * 256) + ((((unsigned)kb >> 4) ^ ((unsigned)row & 7u)) << 4)
         + ((unsigned)kb & 15u);
}

// ---------------- mma.sync m16n8k16 bf16 ----------------
__device__ __forceinline__ void mma_bf16(float c[4], const unsigned a[4], const unsigned b[2]) {
    asm volatile(
        "mma.sync.aligned.m16n8k16.row.col.f32.bf16.bf16.f32 "
        "{%0,%1,%2,%3}, {%4,%5,%6,%7}, {%8,%9}, {%0,%1,%2,%3};"
        : "+f"(c[0]), "+f"(c[1]), "+f"(c[2]), "+f"(c[3])
        : "r"(a[0]), "r"(a[1]), "r"(a[2]), "r"(a[3]), "r"(b[0]), "r"(b[1]));
}

// ---------------- setup: zero + dtype probe + wconv(W2,W3) + fold ----------------
__global__ void k_setup(const void* ei, const void* batch,
                        const float* __restrict__ W2, const float* __restrict__ W3,
                        const float* __restrict__ W4, const float* __restrict__ b4,
                        const float* __restrict__ Wlin, const float* __restrict__ blin) {
    int bid = blockIdx.x;
    if (bid < 512) {                       // zeroing
        int i = bid * 256 + threadIdx.x;
        int stride = 512 * 256;
        for (int t = i; t < NN; t += stride) { d_counts[t] = 0; d_cursor[t] = 0; }
        for (int t = i; t < NGR * 2; t += stride) d_pool2[t] = 0.f;
        for (int t = i; t < NGR; t += stride) d_gcnt[t] = 0;
    } else if (bid == 512) {               // dtype probe
        if (threadIdx.x < 32) {
            const int* w1 = (const int*)ei;
            const int* w2 = (const int*)batch;
            int lane = threadIdx.x;
            int nz1 = 0, nz2 = 0;
            for (int i = 2 * lane + 1; i < 4096; i += 64) { nz1 |= w1[i]; nz2 |= w2[i]; }
            nz1 = __reduce_or_sync(0xffffffffu, nz1);
            nz2 = __reduce_or_sync(0xffffffffu, nz2);
            if (lane == 0) { d_is64_ei = (nz1 == 0); d_is64_batch = (nz2 == 0); }
        }
    } else if (bid < 577) {                // wconv: split-bf16 transposed W tiles
        int idx64 = bid - 513;             // 0..63
        int sel = idx64 >> 5;
        const float* W = sel ? W3 : W2;
        int idx = (idx64 & 31) * 256 + threadIdx.x;   // < 8192
        int n = idx >> 6;
        int k = (idx & 63) * 2;
        float v0 = W[k * HID + n];
        float v1 = W[(k + 1) * HID + n];
        unsigned short h0 = bfh(v0), h1 = bfh(v1);
        unsigned short l0 = bfh(v0 - bf2f(h0)), l1 = bfh(v1 - bf2f(h1));
        unsigned off = sw_off(n, k * 2);
        unsigned char* bh = sel ? d_B3hi : d_B2hi;
        unsigned char* bl = sel ? d_B3lo : d_B2lo;
        *(unsigned*)(bh + off) = (unsigned)h0 | ((unsigned)h1 << 16);
        *(unsigned*)(bl + off) = (unsigned)l0 | ((unsigned)l1 << 16);
    } else {                               // fold: W4p = W4 @ Wlin, b4p
        int j = threadIdx.x;
        if (j >= HID) return;
        float s0 = 0.f, s1 = 0.f;
#pragma unroll 8
        for (int k = 0; k < HID; k++) {
            float w = W4[j * HID + k];
            s0 += w * Wlin[k * 2 + 0];
            s1 += w * Wlin[k * 2 + 1];
        }
        d_W4p[j * 2 + 0] = s0;
        d_W4p[j * 2 + 1] = s1;
        if (j < 2) {
            float s = 0.f;
            for (int k = 0; k < HID; k++) s += b4[k] * Wlin[k * 2 + j];
            d_b4p[j] = s + blin[j];
        }
    }
}

// ---------------- degree histogram + nodes-per-graph histogram ----------------
__global__ void __launch_bounds__(256) k_hist(const void* __restrict__ ei,
                                              const void* __restrict__ batch) {
    __shared__ int sh[NGR];
    if (blockIdx.x < HB) {
        int e = blockIdx.x * 256 + threadIdx.x;
        if (e >= NE) return;
        unsigned d = (unsigned)load_idx(ei, d_is64_ei, (long long)NE + e);
        if (d < NN) atomicAdd(&d_counts[d], 1);
    } else {
        for (int t = threadIdx.x; t < NGR; t += 256) sh[t] = 0;
        __syncthreads();
        int is64 = d_is64_batch;
        for (int i = (blockIdx.x - HB) * 256 + threadIdx.x; i < NN; i += 64 * 256) {
            unsigned g = (unsigned)load_idx(batch, is64, i);
            if (g < NGR) atomicAdd(&sh[g], 1);
        }
        __syncthreads();
        for (int t = threadIdx.x; t < NGR; t += 256)
            if (sh[t]) atomicAdd(&d_gcnt[t], sh[t]);
    }
}

// ---------------- scan phase 1: per-block reduce (+dinv) ----------------
__global__ void __launch_bounds__(1024) k_scan1() {
    __shared__ int ws[32];
    int i = blockIdx.x * 1024 + threadIdx.x;
    int v = 0;
    if (i < NN) {
        v = d_counts[i];
        d_dinv[i] = rsqrtf((float)v + 1.0f);
    }
    int s = v;
#pragma unroll
    for (int o = 16; o > 0; o >>= 1) s += __shfl_down_sync(0xffffffffu, s, o);
    if ((threadIdx.x & 31) == 0) ws[threadIdx.x >> 5] = s;
    __syncthreads();
    if (threadIdx.x < 32) {
        int t = ws[threadIdx.x];
#pragma unroll
        for (int o = 16; o > 0; o >>= 1) t += __shfl_down_sync(0xffffffffu, t, o);
        if (threadIdx.x == 0) d_bsum[blockIdx.x] = t;
    }
}

// ---------------- scan phases 2+3: base from partials + block scan -> d_off -------
__global__ void __launch_bounds__(1024) k_scan23() {
    __shared__ int sc[32];
    __shared__ int wsum[32];
    __shared__ int sbase;
    int t = threadIdx.x;
    if (t == 0) {
        int base = 0, tot = 0;
        for (int b = 0; b < SB; b++) {
            int v = d_bsum[b];
            if (b < (int)blockIdx.x) base += v;
            tot += v;
        }
        sbase = base;
        if (blockIdx.x == 0) d_off[NN] = tot;
    }
    int i = blockIdx.x * 1024 + t;
    int v = (i < NN) ? d_counts[i] : 0;
    int incl = v;
#pragma unroll
    for (int o = 1; o < 32; o <<= 1) {
        int n = __shfl_up_sync(0xffffffffu, incl, o);
        if ((t & 31) >= o) incl += n;
    }
    if ((t & 31) == 31) wsum[t >> 5] = incl;
    __syncthreads();
    if (t < 32) {
        int w = wsum[t];
#pragma unroll
        for (int o = 1; o < 32; o <<= 1) {
            int n = __shfl_up_sync(0xffffffffu, w, o);
            if (t >= o) w += n;
        }
        sc[t] = w;
    }
    __syncthreads();
    int warp = t >> 5;
    int base = sbase + (warp ? sc[warp - 1] : 0);
    if (i < NN) d_off[i] = base + incl - v;
}

// ---------------- scatter edges into CSR (by dst); norm factored out ----------------
__global__ void k_scatter(const void* __restrict__ ei) {
    int e = blockIdx.x * blockDim.x + threadIdx.x;
    if (e >= NE) return;
    int is64 = d_is64_ei;
    unsigned s = (unsigned)load_idx(ei, is64, e);
    unsigned d = (unsigned)load_idx(ei, is64, (long long)NE + e);
    if (s >= NN || d >= NN) return;
    int pos = d_off[d] + atomicAdd(&d_cursor[d], 1);
    d_csrc[pos] = (int)s;
}

// ---------------- fused: (ÂX)W1 + b1, relu -> split-bf16 A tiles ----------------
__global__ void __launch_bounds__(128) k_aggx7(const float* __restrict__ x,
                                               const float* __restrict__ W1,
                                               const float* __restrict__ b1) {
    __shared__ float sax[16][8];
    __shared__ float sW[FIN * HID];
    __shared__ float sb[HID];
    const int tid = threadIdx.x;
    for (int t = tid; t < FIN * HID; t += 128) sW[t] = W1[t];
    sb[tid] = b1[tid];

    const int sub = tid & 7;
    const int local = tid >> 3;
    const int i = blockIdx.x * 16 + local;          // always < NN
    const int col = (sub < 7) ? sub : 6;
    const float di = d_dinv[i];
    float acc = di * x[i * 7 + col];
    int e = d_off[i];
    const int e1 = d_off[i + 1];
    for (; e + 2 <= e1; e += 2) {
        int s0 = d_csrc[e], s1 = d_csrc[e + 1];
        float w0 = d_dinv[s0], w1 = d_dinv[s1];
        acc += w0 * x[s0 * 7 + col] + w1 * x[s1 * 7 + col];
    }
    if (e < e1) { int s = d_csrc[e]; acc += d_dinv[s] * x[s * 7 + col]; }
    sax[local][sub] = acc * di;
    __syncthreads();

#pragma unroll
    for (int j = 0; j < 8; j++) {
        int task = tid + j * 128;
        int node = task >> 6;
        int jp = (task & 63) * 2;
        float a0 = sb[jp], a1 = sb[jp + 1];
#pragma unroll
        for (int k = 0; k < FIN; k++) {
            float a = sax[node][k];
            a0 += a * sW[k * HID + jp];
            a1 += a * sW[k * HID + jp + 1];
        }
        a0 = fmaxf(a0, 0.f); a1 = fmaxf(a1, 0.f);
        unsigned short h0 = bfh(a0), h1 = bfh(a1);
        unsigned short l0 = bfh(a0 - bf2f(h0)), l1 = bfh(a1 - bf2f(h1));
        int row = blockIdx.x * 16 + node;
        unsigned off = sw_off(row, jp * 2);
        *(unsigned*)(d_Ahi + off) = (unsigned)h0 | ((unsigned)h1 << 16);
        *(unsigned*)(d_Alo + off) = (unsigned)l0 | ((unsigned)l1 << 16);
    }
}

// ---------------- 128x128 GEMM via mma.sync bf16x3, 4 A-tiles per CTA --------------
// 256 threads; B (hi+lo) loaded ONCE per CTA, reused across 4x64 rows.
__global__ void __launch_bounds__(256) k_gemm128(int sel) {
    extern __shared__ __align__(16) unsigned char smem[];
    unsigned char* As_hi = smem;            // 64*256 = 16 KB
    unsigned char* As_lo = smem + 16384;
    unsigned char* Bs_hi = smem + 32768;    // 128*256 = 32 KB
    unsigned char* Bs_lo = smem + 65536;
    const int tid = threadIdx.x;

    // load B tiles once
    {
        const uint4* bh = (const uint4*)(sel ? d_B3hi : d_B2hi);
        const uint4* bl = (const uint4*)(sel ? d_B3lo : d_B2lo);
        uint4* sbh = (uint4*)Bs_hi;
        uint4* sbl = (uint4*)Bs_lo;
#pragma unroll
        for (int i = 0; i < 8; i++) sbh[tid + i * 256] = bh[tid + i * 256];
#pragma unroll
        for (int i = 0; i < 8; i++) sbl[tid + i * 256] = bl[tid + i * 256];
    }

    const int w = tid >> 5, lane = tid & 31;
    const int wm = (w & 1) * 32;
    const int wn = (w >> 1) * 32;
    const int lr = lane >> 2;
    const int kq = (lane & 3) * 4;

    for (int t = 0; t < 4; t++) {
        const int tile = blockIdx.x * 4 + t;
        // load A tile (pre-split swizzled image)
        {
            const uint4* ah = (const uint4*)d_Ahi + (size_t)tile * 1024;
            const uint4* al = (const uint4*)d_Alo + (size_t)tile * 1024;
            uint4* sah = (uint4*)As_hi;
            uint4* sal = (uint4*)As_lo;
#pragma unroll
            for (int i = 0; i < 4; i++) sah[tid + i * 256] = ah[tid + i * 256];
#pragma unroll
            for (int i = 0; i < 4; i++) sal[tid + i * 256] = al[tid + i * 256];
        }
        __syncthreads();

        float c[2][4][4] = {};

#pragma unroll
        for (int ks = 0; ks < 8; ks++) {
            const int kb0 = ks * 32;
            unsigned ah[2][4], al[2][4], bh[4][2], bl[4][2];
#pragma unroll
            for (int mt = 0; mt < 2; mt++) {
                int r = wm + mt * 16 + lr;
                ah[mt][0] = *(const unsigned*)(As_hi + sw_off(r,     kb0 + kq));
                ah[mt][1] = *(const unsigned*)(As_hi + sw_off(r + 8, kb0 + kq));
                ah[mt][2] = *(const unsigned*)(As_hi + sw_off(r,     kb0 + 16 + kq));
                ah[mt][3] = *(const unsigned*)(As_hi + sw_off(r + 8, kb0 + 16 + kq));
                al[mt][0] = *(const unsigned*)(As_lo + sw_off(r,     kb0 + kq));
                al[mt][1] = *(const unsigned*)(As_lo + sw_off(r + 8, kb0 + kq));
                al[mt][2] = *(const unsigned*)(As_lo + sw_off(r,     kb0 + 16 + kq));
                al[mt][3] = *(const unsigned*)(As_lo + sw_off(r + 8, kb0 + 16 + kq));
            }
#pragma unroll
            for (int nt = 0; nt < 4; nt++) {
                int n = wn + nt * 8 + lr;
                bh[nt][0] = *(const unsigned*)(Bs_hi + sw_off(n, kb0 + kq));
                bh[nt][1] = *(const unsigned*)(Bs_hi + sw_off(n, kb0 + 16 + kq));
                bl[nt][0] = *(const unsigned*)(Bs_lo + sw_off(n, kb0 + kq));
                bl[nt][1] = *(const unsigned*)(Bs_lo + sw_off(n, kb0 + 16 + kq));
            }
#pragma unroll
            for (int mt = 0; mt < 2; mt++)
#pragma unroll
                for (int nt = 0; nt < 4; nt++) {
                    mma_bf16(c[mt][nt], ah[mt], bh[nt]);
                    mma_bf16(c[mt][nt], ah[mt], bl[nt]);
                    mma_bf16(c[mt][nt], al[mt], bh[nt]);
                }
        }

        const int node0 = tile * 64;
#pragma unroll
        for (int mt = 0; mt < 2; mt++) {
#pragma unroll
            for (int nt = 0; nt < 4; nt++) {
                int row = node0 + wm + mt * 16 + lr;
                int col = wn + nt * 8 + (lane & 3) * 2;
                *(float2*)&d_hw[(size_t)row * HID + col] = make_float2(c[mt][nt][0], c[mt][nt][1]);
                *(float2*)&d_hw[(size_t)(row + 8) * HID + col] = make_float2(c[mt][nt][2], c[mt][nt][3]);
            }
        }
        __syncthreads();   // A buffer reuse guard
    }
}

// ---------------- aggregation core (warp/node, float4/lane, unroll 8) --------------
// returns dinv_i * (dinv_i*v_i + sum dinv_s*v_s) + b
__device__ __forceinline__ float4 agg_core(int i, int lane, const float* __restrict__ b) {
    const float4* hw4 = (const float4*)d_hw;
    const float di = d_dinv[i];
    float4 acc = hw4[(size_t)i * 32 + lane];
    acc.x *= di; acc.y *= di; acc.z *= di; acc.w *= di;
    int e = d_off[i];
    const int e1 = d_off[i + 1];
    for (; e + 8 <= e1; e += 8) {
        int s[8]; float ds[8]; float4 v[8];
#pragma unroll
        for (int j = 0; j < 8; j++) s[j] = d_csrc[e + j];
#pragma unroll
        for (int j = 0; j < 8; j++) ds[j] = d_dinv[s[j]];
#pragma unroll
        for (int j = 0; j < 8; j++) v[j] = hw4[(size_t)s[j] * 32 + lane];
#pragma unroll
        for (int j = 0; j < 8; j++) {
            acc.x += ds[j] * v[j].x; acc.y += ds[j] * v[j].y;
            acc.z += ds[j] * v[j].z; acc.w += ds[j] * v[j].w;
        }
    }
    for (; e < e1; e++) {
        int s = d_csrc[e];
        float ds = d_dinv[s];
        float4 v = hw4[(size_t)s * 32 + lane];
        acc.x += ds * v.x; acc.y += ds * v.y; acc.z += ds * v.z; acc.w += ds * v.w;
    }
    float4 bv = ((const float4*)b)[lane];
    acc.x = acc.x * di + bv.x; acc.y = acc.y * di + bv.y;
    acc.z = acc.z * di + bv.z; acc.w = acc.w * di + bv.w;
    return acc;
}

// layer-2 aggregation: emit relu'd split-bf16 A tiles for the next GEMM
__global__ void __launch_bounds__(128) k_aggT(const float* __restrict__ b) {
    const int lane = threadIdx.x & 31;
    const int i = blockIdx.x * 4 + (threadIdx.x >> 5);
    if (i >= NN) return;
    float4 acc = agg_core(i, lane, b);
    acc.x = fmaxf(acc.x, 0.f); acc.y = fmaxf(acc.y, 0.f);
    acc.z = fmaxf(acc.z, 0.f); acc.w = fmaxf(acc.w, 0.f);
    unsigned short h0 = bfh(acc.x), h1 = bfh(acc.y), h2 = bfh(acc.z), h3 = bfh(acc.w);
    unsigned short l0 = bfh(acc.x - bf2f(h0)), l1 = bfh(acc.y - bf2f(h1));
    unsigned short l2 = bfh(acc.z - bf2f(h2)), l3 = bfh(acc.w - bf2f(h3));
    unsigned long long ph = (unsigned long long)((unsigned)h0 | ((unsigned)h1 << 16))
                          | ((unsigned long long)((unsigned)h2 | ((unsigned)h3 << 16)) << 32);
    unsigned long long pl = (unsigned long long)((unsigned)l0 | ((unsigned)l1 << 16))
                          | ((unsigned long long)((unsigned)l2 | ((unsigned)l3 << 16)) << 32);
    unsigned off = sw_off(i, lane * 8);
    *(unsigned long long*)(d_Ahi + off) = ph;
    *(unsigned long long*)(d_Alo + off) = pl;
}

// layer-3 aggregation fused with folded layer-4 GEMV: d_t = relu(agg) @ W4p
__global__ void __launch_bounds__(128) k_aggG(const float* __restrict__ b) {
    __shared__ float sw[HID * 2];
    const int tid = threadIdx.x;
    sw[tid] = d_W4p[tid];
    sw[tid + 128] = d_W4p[tid + 128];
    __syncthreads();

    const int lane = tid & 31;
    const int i = blockIdx.x * 4 + (tid >> 5);
    if (i >= NN) return;
    float4 a = agg_core(i, lane, b);
    a.x = fmaxf(a.x, 0.f); a.y = fmaxf(a.y, 0.f);
    a.z = fmaxf(a.z, 0.f); a.w = fmaxf(a.w, 0.f);
    const int j0 = lane * 4;
    float s0 = a.x * sw[(j0+0)*2]   + a.y * sw[(j0+1)*2]   + a.z * sw[(j0+2)*2]   + a.w * sw[(j0+3)*2];
    float s1 = a.x * sw[(j0+0)*2+1] + a.y * sw[(j0+1)*2+1] + a.z * sw[(j0+2)*2+1] + a.w * sw[(j0+3)*2+1];
#pragma unroll
    for (int o = 16; o > 0; o >>= 1) {
        s0 += __shfl_down_sync(0xffffffffu, s0, o);
        s1 += __shfl_down_sync(0xffffffffu, s1, o);
    }
    if (lane == 0) {
        d_t[i * 2 + 0] = s0;
        d_t[i * 2 + 1] = s1;
    }
}

// ---------------- 2-wide aggregation fused with pooling (warp-agg atomics) ---------
__global__ void k_agg2pool(const void* __restrict__ batch) {
    int i = blockIdx.x * blockDim.x + threadIdx.x;
    bool valid = i < NN;
    float a0 = 0.f, a1 = 0.f;
    unsigned g = 0xffffffffu;
    if (valid) {
        const float2* t2 = (const float2*)d_t;
        const float di = d_dinv[i];
        float2 ti = t2[i];
        a0 = di * ti.x; a1 = di * ti.y;
        const int e1 = d_off[i + 1];
        for (int e = d_off[i]; e < e1; e++) {
            int s = d_csrc[e];
            float ds = d_dinv[s];
            float2 ts = t2[s];
            a0 += ds * ts.x; a1 += ds * ts.y;
        }
        a0 *= di; a1 *= di;
        g = (unsigned)load_idx(batch, d_is64_batch, i);
    }
    unsigned g0 = __shfl_sync(0xffffffffu, g, 0);
    bool uni = __all_sync(0xffffffffu, g == g0);
    if (uni && g0 < NGR) {
#pragma unroll
        for (int o = 16; o > 0; o >>= 1) {
            a0 += __shfl_down_sync(0xffffffffu, a0, o);
            a1 += __shfl_down_sync(0xffffffffu, a1, o);
        }
        if ((threadIdx.x & 31) == 0) {
            atomicAdd(&d_pool2[g0 * 2 + 0], a0);
            atomicAdd(&d_pool2[g0 * 2 + 1], a1);
        }
    } else if (valid && g < NGR) {
        atomicAdd(&d_pool2[g * 2 + 0], a0);
        atomicAdd(&d_pool2[g * 2 + 1], a1);
    }
}

// ---------------- output: mean + folded bias ----------------
__global__ void k_out(float* __restrict__ out) {
    int idx = blockIdx.x * blockDim.x + threadIdx.x;
    if (idx >= NGR * 2) return;
    int g = idx >> 1, c = idx & 1;
    float cnt = fmaxf((float)d_gcnt[g], 1.0f);
    out[idx] = d_pool2[g * 2 + c] / cnt + d_b4p[c];
}

// ---------------- launch ----------------
extern "C" void kernel_launch(void* const* d_in, const int* in_sizes, int n_in,
                              void* d_out, int out_size) {
    // Resolve inputs by element count — robust to metadata ordering.
    int ix = 0, iei = 1, ibatch = 2, iW1 = 3, iWlin = 11, iblin = 12;
    int iW[3] = {5, 7, 9};
    int ib[4] = {4, 6, 8, 10};
    {
        int nW = 0, nb = 0;
        int fx = -1, fei = -1, fb = -1, fW1 = -1, fWl = -1, fbl = -1;
        int fW[3] = {-1, -1, -1}, fbias[4] = {-1, -1, -1, -1};
        for (int i = 0; i < n_in; i++) {
            switch (in_sizes[i]) {
                case 700000:  fx  = i; break;
                case 3200000: fei = i; break;
                case 100000:  fb  = i; break;
                case 896:     fW1 = i; break;
                case 16384:   if (nW < 3) fW[nW++] = i; break;
                case 128:     if (nb < 4) fbias[nb++] = i; break;
                case 256:     fWl = i; break;
                case 2:       fbl = i; break;
                default: break;
            }
        }
        if (fx >= 0 && fei >= 0 && fb >= 0 && fW1 >= 0 && fWl >= 0 && fbl >= 0 &&
            nW == 3 && nb == 4) {
            ix = fx; iei = fei; ibatch = fb; iW1 = fW1; iWlin = fWl; iblin = fbl;
            iW[0] = fW[0]; iW[1] = fW[1]; iW[2] = fW[2];
            ib[0] = fbias[0]; ib[1] = fbias[1]; ib[2] = fbias[2]; ib[3] = fbias[3];
        }
    }

    const float* x     = (const float*)d_in[ix];
    const void*  ei    = d_in[iei];
    const void*  batch = d_in[ibatch];
    float* out = (float*)d_out;

    const int GEMM_SMEM = 96 * 1024;
    cudaFuncSetAttribute(k_gemm128, cudaFuncAttributeMaxDynamicSharedMemorySize, GEMM_SMEM);

    k_setup<<<578, 256>>>(ei, batch,
                          (const float*)d_in[iW[0]], (const float*)d_in[iW[1]],
                          (const float*)d_in[iW[2]], (const float*)d_in[ib[3]],
                          (const float*)d_in[iWlin], (const float*)d_in[iblin]);
    k_hist<<<HB + 64, 256>>>(ei, batch);
    k_scan1<<<SB, 1024>>>();
    k_scan23<<<SB, 1024>>>();
    k_scatter<<<(NE + 255) / 256, 256>>>(ei);

    // layer 1: fused (ÂX)W1 + b1, relu -> split tiles
    k_aggx7<<<NN / 16, 128>>>(x, (const float*)d_in[iW1], (const float*)d_in[ib[0]]);
    // layer 2: MMA (B reused across 4 tiles/CTA) + aggregation (emit tiles for layer 3)
    k_gemm128<<<NNP / 256, 256, GEMM_SMEM>>>(0);
    k_aggT<<<NN / 4, 128>>>((const float*)d_in[ib[1]]);
    // layer 3: MMA + aggregation fused with folded layer-4 GEMV
    k_gemm128<<<NNP / 256, 256, GEMM_SMEM>>>(1);
    k_aggG<<<NN / 4, 128>>>((const float*)d_in[ib[2]]);
    // pooled 2-wide aggregation + head
    k_agg2pool<<<(NN + 255) / 256, 256>>>(batch);
    k_out<<<(NGR * 2 + 255) / 256, 256>>>(out);
}

// round 14
// speedup vs baseline: 1.5836x; 1.1117x over previous
#include <cuda_runtime.h>
#include <cuda_bf16.h>
#include <cstdint>

#define NN  100000
#define NNP 100032          // 1563 tiles of 64 rows (pad rows stay zero)
#define NE  1600000
#define NGR 512
#define FIN 7
#define HID 128
#define HB  6250            // edge-hist blocks
#define SB  98              // scan blocks (98*1024 >= NN)

// ---------------- scratch (static device globals; zero-initialized) ----------------
__device__ __align__(16) unsigned d_Hh[(size_t)NNP * 64];   // GEMM out, bf16 pairs [row][64]
__device__ __align__(16) float d_t [(size_t)NN * 2];
// A hi/lo bf16 tiles: [row][256B] XOR-granule swizzled (pad rows stay zero)
__device__ __align__(16) unsigned char d_Ahi[(size_t)NNP * 256];
__device__ __align__(16) unsigned char d_Alo[(size_t)NNP * 256];
// W hi/lo bf16, transposed [n][k], 256B rows, swizzled (32 KB each)
__device__ __align__(16) unsigned char d_B2hi[32768], d_B2lo[32768];
__device__ __align__(16) unsigned char d_B3hi[32768], d_B3lo[32768];
__device__ float d_dinv[NN];
__device__ int   d_counts[NN];
__device__ int   d_cursor[NN];
__device__ int   d_off[NN + 1];
__device__ int   d_bsum[SB];
__device__ int   d_csrc[NE];
__device__ float d_pool2[NGR * 2];
__device__ int   d_gcnt[NGR];
__device__ float d_W4p[HID * 2];
__device__ float d_b4p[2];
__device__ int   d_is64_ei;
__device__ int   d_is64_batch;

__device__ __forceinline__ int load_idx(const void* p, int is64, long long i) {
    return is64 ? (int)((const long long*)p)[i] : ((const int*)p)[i];
}

// ---------------- bf16 helpers (pure value ops — no address-taking) ----------------
__device__ __forceinline__ unsigned short bfh(float v) {
    return __bfloat16_as_ushort(__float2bfloat16(v));
}
__device__ __forceinline__ float bf2f(unsigned short u) {
    return __bfloat162float(__ushort_as_bfloat16(u));
}
// pack two fp32 into bf16x2 (lo in lower 16 bits), register-only asm
__device__ __forceinline__ unsigned packbf2(float lo, float hi) {
    unsigned r;
    asm("cvt.rn.bf16x2.f32 %0, %1, %2;" : "=r"(r) : "f"(hi), "f"(lo));
    return r;
}

// swizzled byte offset within a [rows][256B] bf16 image: 16B granules XORed by row&7
__device__ __forceinline__ unsigned sw_off(int row, int kb) {
    return (unsigned)(row * 256) + ((((unsigned)kb >> 4) ^ ((unsigned)row & 7u)) << 4)
         + ((unsigned)kb & 15u);
}

// ---------------- mma.sync m16n8k16 bf16 ----------------
__device__ __forceinline__ void mma_bf16(float c[4], const unsigned a[4], const unsigned b[2]) {
    asm volatile(
        "mma.sync.aligned.m16n8k16.row.col.f32.bf16.bf16.f32 "
        "{%0,%1,%2,%3}, {%4,%5,%6,%7}, {%8,%9}, {%0,%1,%2,%3};"
        : "+f"(c[0]), "+f"(c[1]), "+f"(c[2]), "+f"(c[3])
        : "r"(a[0]), "r"(a[1]), "r"(a[2]), "r"(a[3]), "r"(b[0]), "r"(b[1]));
}

// ---------------- setup: zero + dtype probe + wconv(W2,W3) + fold ----------------
__global__ void k_setup(const void* ei, const void* batch,
                        const float* __restrict__ W2, const float* __restrict__ W3,
                        const float* __restrict__ W4, const float* __restrict__ b4,
                        const float* __restrict__ Wlin, const float* __restrict__ blin) {
    int bid = blockIdx.x;
    if (bid < 512) {                       // zeroing
        int i = bid * 256 + threadIdx.x;
        int stride = 512 * 256;
        for (int t = i; t < NN; t += stride) { d_counts[t] = 0; d_cursor[t] = 0; }
        for (int t = i; t < NGR * 2; t += stride) d_pool2[t] = 0.f;
        for (int t = i; t < NGR; t += stride) d_gcnt[t] = 0;
    } else if (bid == 512) {               // dtype probe
        if (threadIdx.x < 32) {
            const int* w1 = (const int*)ei;
            const int* w2 = (const int*)batch;
            int lane = threadIdx.x;
            int nz1 = 0, nz2 = 0;
            for (int i = 2 * lane + 1; i < 4096; i += 64) { nz1 |= w1[i]; nz2 |= w2[i]; }
            nz1 = __reduce_or_sync(0xffffffffu, nz1);
            nz2 = __reduce_or_sync(0xffffffffu, nz2);
            if (lane == 0) { d_is64_ei = (nz1 == 0); d_is64_batch = (nz2 == 0); }
        }
    } else if (bid < 577) {                // wconv: split-bf16 transposed W tiles
        int idx64 = bid - 513;             // 0..63
        int sel = idx64 >> 5;
        const float* W = sel ? W3 : W2;
        int idx = (idx64 & 31) * 256 + threadIdx.x;   // < 8192
        int n = idx >> 6;
        int k = (idx & 63) * 2;
        float v0 = W[k * HID + n];
        float v1 = W[(k + 1) * HID + n];
        unsigned short h0 = bfh(v0), h1 = bfh(v1);
        unsigned short l0 = bfh(v0 - bf2f(h0)), l1 = bfh(v1 - bf2f(h1));
        unsigned off = sw_off(n, k * 2);
        unsigned char* bh = sel ? d_B3hi : d_B2hi;
        unsigned char* bl = sel ? d_B3lo : d_B2lo;
        *(unsigned*)(bh + off) = (unsigned)h0 | ((unsigned)h1 << 16);
        *(unsigned*)(bl + off) = (unsigned)l0 | ((unsigned)l1 << 16);
    } else {                               // fold: W4p = W4 @ Wlin, b4p
        int j = threadIdx.x;
        if (j >= HID) return;
        float s0 = 0.f, s1 = 0.f;
#pragma unroll 8
        for (int k = 0; k < HID; k++) {
            float w = W4[j * HID + k];
            s0 += w * Wlin[k * 2 + 0];
            s1 += w * Wlin[k * 2 + 1];
        }
        d_W4p[j * 2 + 0] = s0;
        d_W4p[j * 2 + 1] = s1;
        if (j < 2) {
            float s = 0.f;
            for (int k = 0; k < HID; k++) s += b4[k] * Wlin[k * 2 + j];
            d_b4p[j] = s + blin[j];
        }
    }
}

// ---------------- degree histogram + nodes-per-graph histogram ----------------
__global__ void __launch_bounds__(256) k_hist(const void* __restrict__ ei,
                                              const void* __restrict__ batch) {
    __shared__ int sh[NGR];
    if (blockIdx.x < HB) {
        int e = blockIdx.x * 256 + threadIdx.x;
        if (e >= NE) return;
        unsigned d = (unsigned)load_idx(ei, d_is64_ei, (long long)NE + e);
        if (d < NN) atomicAdd(&d_counts[d], 1);
    } else {
        for (int t = threadIdx.x; t < NGR; t += 256) sh[t] = 0;
        __syncthreads();
        int is64 = d_is64_batch;
        for (int i = (blockIdx.x - HB) * 256 + threadIdx.x; i < NN; i += 64 * 256) {
            unsigned g = (unsigned)load_idx(batch, is64, i);
            if (g < NGR) atomicAdd(&sh[g], 1);
        }
        __syncthreads();
        for (int t = threadIdx.x; t < NGR; t += 256)
            if (sh[t]) atomicAdd(&d_gcnt[t], sh[t]);
    }
}

// ---------------- scan phase 1: per-block reduce (+dinv) ----------------
__global__ void __launch_bounds__(1024) k_scan1() {
    __shared__ int ws[32];
    int i = blockIdx.x * 1024 + threadIdx.x;
    int v = 0;
    if (i < NN) {
        v = d_counts[i];
        d_dinv[i] = rsqrtf((float)v + 1.0f);
    }
    int s = v;
#pragma unroll
    for (int o = 16; o > 0; o >>= 1) s += __shfl_down_sync(0xffffffffu, s, o);
    if ((threadIdx.x & 31) == 0) ws[threadIdx.x >> 5] = s;
    __syncthreads();
    if (threadIdx.x < 32) {
        int t = ws[threadIdx.x];
#pragma unroll
        for (int o = 16; o > 0; o >>= 1) t += __shfl_down_sync(0xffffffffu, t, o);
        if (threadIdx.x == 0) d_bsum[blockIdx.x] = t;
    }
}

// ---------------- scan phases 2+3: base from partials + block scan -> d_off -------
__global__ void __launch_bounds__(1024) k_scan23() {
    __shared__ int sc[32];
    __shared__ int wsum[32];
    __shared__ int sbase;
    int t = threadIdx.x;
    if (t == 0) {
        int base = 0, tot = 0;
        for (int b = 0; b < SB; b++) {
            int v = d_bsum[b];
            if (b < (int)blockIdx.x) base += v;
            tot += v;
        }
        sbase = base;
        if (blockIdx.x == 0) d_off[NN] = tot;
    }
    int i = blockIdx.x * 1024 + t;
    int v = (i < NN) ? d_counts[i] : 0;
    int incl = v;
#pragma unroll
    for (int o = 1; o < 32; o <<= 1) {
        int n = __shfl_up_sync(0xffffffffu, incl, o);
        if ((t & 31) >= o) incl += n;
    }
    if ((t & 31) == 31) wsum[t >> 5] = incl;
    __syncthreads();
    if (t < 32) {
        int w = wsum[t];
#pragma unroll
        for (int o = 1; o < 32; o <<= 1) {
            int n = __shfl_up_sync(0xffffffffu, w, o);
            if (t >= o) w += n;
        }
        sc[t] = w;
    }
    __syncthreads();
    int warp = t >> 5;
    int base = sbase + (warp ? sc[warp - 1] : 0);
    if (i < NN) d_off[i] = base + incl - v;
}

// ---------------- scatter edges into CSR (by dst); norm factored out ----------------
__global__ void k_scatter(const void* __restrict__ ei) {
    int e = blockIdx.x * blockDim.x + threadIdx.x;
    if (e >= NE) return;
    int is64 = d_is64_ei;
    unsigned s = (unsigned)load_idx(ei, is64, e);
    unsigned d = (unsigned)load_idx(ei, is64, (long long)NE + e);
    if (s >= NN || d >= NN) return;
    int pos = d_off[d] + atomicAdd(&d_cursor[d], 1);
    d_csrc[pos] = (int)s;
}

// ---------------- fused: (ÂX)W1 + b1, relu -> split-bf16 A tiles ----------------
__global__ void __launch_bounds__(128) k_aggx7(const float* __restrict__ x,
                                               const float* __restrict__ W1,
                                               const float* __restrict__ b1) {
    __shared__ float sax[16][8];
    __shared__ float sW[FIN * HID];
    __shared__ float sb[HID];
    const int tid = threadIdx.x;
    for (int t = tid; t < FIN * HID; t += 128) sW[t] = W1[t];
    sb[tid] = b1[tid];

    const int sub = tid & 7;
    const int local = tid >> 3;
    const int i = blockIdx.x * 16 + local;          // always < NN
    const int col = (sub < 7) ? sub : 6;
    const float di = d_dinv[i];
    float acc = di * x[i * 7 + col];
    int e = d_off[i];
    const int e1 = d_off[i + 1];
    for (; e + 2 <= e1; e += 2) {
        int s0 = d_csrc[e], s1 = d_csrc[e + 1];
        float w0 = d_dinv[s0], w1 = d_dinv[s1];
        acc += w0 * x[s0 * 7 + col] + w1 * x[s1 * 7 + col];
    }
    if (e < e1) { int s = d_csrc[e]; acc += d_dinv[s] * x[s * 7 + col]; }
    sax[local][sub] = acc * di;
    __syncthreads();

#pragma unroll
    for (int j = 0; j < 8; j++) {
        int task = tid + j * 128;
        int node = task >> 6;
        int jp = (task & 63) * 2;
        float a0 = sb[jp], a1 = sb[jp + 1];
#pragma unroll
        for (int k = 0; k < FIN; k++) {
            float a = sax[node][k];
            a0 += a * sW[k * HID + jp];
            a1 += a * sW[k * HID + jp + 1];
        }
        a0 = fmaxf(a0, 0.f); a1 = fmaxf(a1, 0.f);
        unsigned short h0 = bfh(a0), h1 = bfh(a1);
        unsigned short l0 = bfh(a0 - bf2f(h0)), l1 = bfh(a1 - bf2f(h1));
        int row = blockIdx.x * 16 + node;
        unsigned off = sw_off(row, jp * 2);
        *(unsigned*)(d_Ahi + off) = (unsigned)h0 | ((unsigned)h1 << 16);
        *(unsigned*)(d_Alo + off) = (unsigned)l0 | ((unsigned)l1 << 16);
    }
}

// ---------------- 128x128 GEMM via mma.sync bf16x3: Atiles @ W -> d_Hh (bf16) ------
// R11 structure: 256 threads, 64 rows x 128 cols/block, 1563 CTAs.
__global__ void __launch_bounds__(256) k_gemm128(int sel) {
    extern __shared__ __align__(16) unsigned char smem[];
    unsigned char* As_hi = smem;            // 64*256 = 16 KB
    unsigned char* As_lo = smem + 16384;
    unsigned char* Bs_hi = smem + 32768;    // 128*256 = 32 KB
    unsigned char* Bs_lo = smem + 65536;
    const int tid = threadIdx.x;

    {
        const uint4* ah = (const uint4*)d_Ahi + (size_t)blockIdx.x * 1024;
        const uint4* al = (const uint4*)d_Alo + (size_t)blockIdx.x * 1024;
        const uint4* bh = (const uint4*)(sel ? d_B3hi : d_B2hi);
        const uint4* bl = (const uint4*)(sel ? d_B3lo : d_B2lo);
        uint4* sah = (uint4*)As_hi;
        uint4* sal = (uint4*)As_lo;
        uint4* sbh = (uint4*)Bs_hi;
        uint4* sbl = (uint4*)Bs_lo;
#pragma unroll
        for (int i = 0; i < 4; i++) sah[tid + i * 256] = ah[tid + i * 256];
#pragma unroll
        for (int i = 0; i < 4; i++) sal[tid + i * 256] = al[tid + i * 256];
#pragma unroll
        for (int i = 0; i < 8; i++) sbh[tid + i * 256] = bh[tid + i * 256];
#pragma unroll
        for (int i = 0; i < 8; i++) sbl[tid + i * 256] = bl[tid + i * 256];
    }
    __syncthreads();

    const int w = tid >> 5, lane = tid & 31;
    const int wm = (w & 1) * 32;
    const int wn = (w >> 1) * 32;
    const int lr = lane >> 2;
    const int kq = (lane & 3) * 4;

    float c[2][4][4] = {};

#pragma unroll
    for (int ks = 0; ks < 8; ks++) {
        const int kb0 = ks * 32;
        unsigned ah[2][4], al[2][4], bh[4][2], bl[4][2];
#pragma unroll
        for (int mt = 0; mt < 2; mt++) {
            int r = wm + mt * 16 + lr;
            ah[mt][0] = *(const unsigned*)(As_hi + sw_off(r,     kb0 + kq));
            ah[mt][1] = *(const unsigned*)(As_hi + sw_off(r + 8, kb0 + kq));
            ah[mt][2] = *(const unsigned*)(As_hi + sw_off(r,     kb0 + 16 + kq));
            ah[mt][3] = *(const unsigned*)(As_hi + sw_off(r + 8, kb0 + 16 + kq));
            al[mt][0] = *(const unsigned*)(As_lo + sw_off(r,     kb0 + kq));
            al[mt][1] = *(const unsigned*)(As_lo + sw_off(r + 8, kb0 + kq));
            al[mt][2] = *(const unsigned*)(As_lo + sw_off(r,     kb0 + 16 + kq));
            al[mt][3] = *(const unsigned*)(As_lo + sw_off(r + 8, kb0 + 16 + kq));
        }
#pragma unroll
        for (int nt = 0; nt < 4; nt++) {
            int n = wn + nt * 8 + lr;
            bh[nt][0] = *(const unsigned*)(Bs_hi + sw_off(n, kb0 + kq));
            bh[nt][1] = *(const unsigned*)(Bs_hi + sw_off(n, kb0 + 16 + kq));
            bl[nt][0] = *(const unsigned*)(Bs_lo + sw_off(n, kb0 + kq));
            bl[nt][1] = *(const unsigned*)(Bs_lo + sw_off(n, kb0 + 16 + kq));
        }
#pragma unroll
        for (int mt = 0; mt < 2; mt++)
#pragma unroll
            for (int nt = 0; nt < 4; nt++) {
                mma_bf16(c[mt][nt], ah[mt], bh[nt]);
                mma_bf16(c[mt][nt], ah[mt], bl[nt]);
                mma_bf16(c[mt][nt], al[mt], bh[nt]);
            }
    }

    // epilogue: bf16x2 packs -> d_Hh (row-major [row][64 uint]) via register-only cvt
    const int node0 = blockIdx.x * 64;
#pragma unroll
    for (int mt = 0; mt < 2; mt++) {
#pragma unroll
        for (int nt = 0; nt < 4; nt++) {
            int row = node0 + wm + mt * 16 + lr;
            int cu = (wn + nt * 8 + (lane & 3) * 2) >> 1;
            d_Hh[(size_t)row * 64 + cu]       = packbf2(c[mt][nt][0], c[mt][nt][1]);
            d_Hh[(size_t)(row + 8) * 64 + cu] = packbf2(c[mt][nt][2], c[mt][nt][3]);
        }
    }
}

// ---------------- aggregation core (warp/node, 4 bf16/lane, unroll 8) --------------
// bf16 -> fp32 via 16-bit shift/mask (pure ALU, no cvt, no address-taking).
// returns dinv_i * (dinv_i*v_i + sum dinv_s*v_s) + b
__device__ __forceinline__ float4 agg_core(int i, int lane, const float* __restrict__ b) {
    const uint2* hw2 = (const uint2*)d_Hh;
    const float di = d_dinv[i];
    uint2 rs = hw2[(size_t)i * 32 + lane];
    float4 acc;
    acc.x = di * __uint_as_float(rs.x << 16);
    acc.y = di * __uint_as_float(rs.x & 0xffff0000u);
    acc.z = di * __uint_as_float(rs.y << 16);
    acc.w = di * __uint_as_float(rs.y & 0xffff0000u);
    int e = d_off[i];
    const int e1 = d_off[i + 1];
    for (; e + 8 <= e1; e += 8) {
        int s[8]; float ds[8]; uint2 r[8];
#pragma unroll
        for (int j = 0; j < 8; j++) s[j] = d_csrc[e + j];
#pragma unroll
        for (int j = 0; j < 8; j++) ds[j] = d_dinv[s[j]];
#pragma unroll
        for (int j = 0; j < 8; j++) r[j] = hw2[(size_t)s[j] * 32 + lane];
#pragma unroll
        for (int j = 0; j < 8; j++) {
            acc.x += ds[j] * __uint_as_float(r[j].x << 16);
            acc.y += ds[j] * __uint_as_float(r[j].x & 0xffff0000u);
            acc.z += ds[j] * __uint_as_float(r[j].y << 16);
            acc.w += ds[j] * __uint_as_float(r[j].y & 0xffff0000u);
        }
    }
    for (; e < e1; e++) {
        int sIdx = d_csrc[e];
        float ds = d_dinv[sIdx];
        uint2 r = hw2[(size_t)sIdx * 32 + lane];
        acc.x += ds * __uint_as_float(r.x << 16);
        acc.y += ds * __uint_as_float(r.x & 0xffff0000u);
        acc.z += ds * __uint_as_float(r.y << 16);
        acc.w += ds * __uint_as_float(r.y & 0xffff0000u);
    }
    float4 bv = ((const float4*)b)[lane];
    acc.x = acc.x * di + bv.x; acc.y = acc.y * di + bv.y;
    acc.z = acc.z * di + bv.z; acc.w = acc.w * di + bv.w;
    return acc;
}

// layer-2 aggregation: emit relu'd split-bf16 A tiles for the next GEMM
__global__ void __launch_bounds__(128) k_aggT(const float* __restrict__ b) {
    const int lane = threadIdx.x & 31;
    const int i = blockIdx.x * 4 + (threadIdx.x >> 5);
    if (i >= NN) return;
    float4 acc = agg_core(i, lane, b);
    acc.x = fmaxf(acc.x, 0.f); acc.y = fmaxf(acc.y, 0.f);
    acc.z = fmaxf(acc.z, 0.f); acc.w = fmaxf(acc.w, 0.f);
    unsigned short h0 = bfh(acc.x), h1 = bfh(acc.y), h2 = bfh(acc.z), h3 = bfh(acc.w);
    unsigned short l0 = bfh(acc.x - bf2f(h0)), l1 = bfh(acc.y - bf2f(h1));
    unsigned short l2 = bfh(acc.z - bf2f(h2)), l3 = bfh(acc.w - bf2f(h3));
    unsigned long long ph = (unsigned long long)((unsigned)h0 | ((unsigned)h1 << 16))
                          | ((unsigned long long)((unsigned)h2 | ((unsigned)h3 << 16)) << 32);
    unsigned long long pl = (unsigned long long)((unsigned)l0 | ((unsigned)l1 << 16))
                          | ((unsigned long long)((unsigned)l2 | ((unsigned)l3 << 16)) << 32);
    unsigned off = sw_off(i, lane * 8);
    *(unsigned long long*)(d_Ahi + off) = ph;
    *(unsigned long long*)(d_Alo + off) = pl;
}

// layer-3 aggregation fused with folded layer-4 GEMV: d_t = relu(agg) @ W4p
__global__ void __launch_bounds__(128) k_aggG(const float* __restrict__ b) {
    __shared__ float sw[HID * 2];
    const int tid = threadIdx.x;
    sw[tid] = d_W4p[tid];
    sw[tid + 128] = d_W4p[tid + 128];
    __syncthreads();

    const int lane = tid & 31;
    const int i = blockIdx.x * 4 + (tid >> 5);
    if (i >= NN) return;
    float4 a = agg_core(i, lane, b);
    a.x = fmaxf(a.x, 0.f); a.y = fmaxf(a.y, 0.f);
    a.z = fmaxf(a.z, 0.f); a.w = fmaxf(a.w, 0.f);
    const int j0 = lane * 4;
    float s0 = a.x * sw[(j0+0)*2]   + a.y * sw[(j0+1)*2]   + a.z * sw[(j0+2)*2]   + a.w * sw[(j0+3)*2];
    float s1 = a.x * sw[(j0+0)*2+1] + a.y * sw[(j0+1)*2+1] + a.z * sw[(j0+2)*2+1] + a.w * sw[(j0+3)*2+1];
#pragma unroll
    for (int o = 16; o > 0; o >>= 1) {
        s0 += __shfl_down_sync(0xffffffffu, s0, o);
        s1 += __shfl_down_sync(0xffffffffu, s1, o);
    }
    if (lane == 0) {
        d_t[i * 2 + 0] = s0;
        d_t[i * 2 + 1] = s1;
    }
}

// ---------------- 2-wide aggregation fused with pooling (warp-agg atomics) ---------
__global__ void k_agg2pool(const void* __restrict__ batch) {
    int i = blockIdx.x * blockDim.x + threadIdx.x;
    bool valid = i < NN;
    float a0 = 0.f, a1 = 0.f;
    unsigned g = 0xffffffffu;
    if (valid) {
        const float2* t2 = (const float2*)d_t;
        const float di = d_dinv[i];
        float2 ti = t2[i];
        a0 = di * ti.x; a1 = di * ti.y;
        const int e1 = d_off[i + 1];
        for (int e = d_off[i]; e < e1; e++) {
            int s = d_csrc[e];
            float ds = d_dinv[s];
            float2 ts = t2[s];
            a0 += ds * ts.x; a1 += ds * ts.y;
        }
        a0 *= di; a1 *= di;
        g = (unsigned)load_idx(batch, d_is64_batch, i);
    }
    unsigned g0 = __shfl_sync(0xffffffffu, g, 0);
    bool uni = __all_sync(0xffffffffu, g == g0);
    if (uni && g0 < NGR) {
#pragma unroll
        for (int o = 16; o > 0; o >>= 1) {
            a0 += __shfl_down_sync(0xffffffffu, a0, o);
            a1 += __shfl_down_sync(0xffffffffu, a1, o);
        }
        if ((threadIdx.x & 31) == 0) {
            atomicAdd(&d_pool2[g0 * 2 + 0], a0);
            atomicAdd(&d_pool2[g0 * 2 + 1], a1);
        }
    } else if (valid && g < NGR) {
        atomicAdd(&d_pool2[g * 2 + 0], a0);
        atomicAdd(&d_pool2[g * 2 + 1], a1);
    }
}

// ---------------- output: mean + folded bias ----------------
__global__ void k_out(float* __restrict__ out) {
    int idx = blockIdx.x * blockDim.x + threadIdx.x;
    if (idx >= NGR * 2) return;
    int g = idx >> 1, c = idx & 1;
    float cnt = fmaxf((float)d_gcnt[g], 1.0f);
    out[idx] = d_pool2[g * 2 + c] / cnt + d_b4p[c];
}

// ---------------- launch ----------------
extern "C" void kernel_launch(void* const* d_in, const int* in_sizes, int n_in,
                              void* d_out, int out_size) {
    // Resolve inputs by element count — robust to metadata ordering.
    int ix = 0, iei = 1, ibatch = 2, iW1 = 3, iWlin = 11, iblin = 12;
    int iW[3] = {5, 7, 9};
    int ib[4] = {4, 6, 8, 10};
    {
        int nW = 0, nb = 0;
        int fx = -1, fei = -1, fb = -1, fW1 = -1, fWl = -1, fbl = -1;
        int fW[3] = {-1, -1, -1}, fbias[4] = {-1, -1, -1, -1};
        for (int i = 0; i < n_in; i++) {
            switch (in_sizes[i]) {
                case 700000:  fx  = i; break;
                case 3200000: fei = i; break;
                case 100000:  fb  = i; break;
                case 896:     fW1 = i; break;
                case 16384:   if (nW < 3) fW[nW++] = i; break;
                case 128:     if (nb < 4) fbias[nb++] = i; break;
                case 256:     fWl = i; break;
                case 2:       fbl = i; break;
                default: break;
            }
        }
        if (fx >= 0 && fei >= 0 && fb >= 0 && fW1 >= 0 && fWl >= 0 && fbl >= 0 &&
            nW == 3 && nb == 4) {
            ix = fx; iei = fei; ibatch = fb; iW1 = fW1; iWlin = fWl; iblin = fbl;
            iW[0] = fW[0]; iW[1] = fW[1]; iW[2] = fW[2];
            ib[0] = fbias[0]; ib[1] = fbias[1]; ib[2] = fbias[2]; ib[3] = fbias[3];
        }
    }

    const float* x     = (const float*)d_in[ix];
    const void*  ei    = d_in[iei];
    const void*  batch = d_in[ibatch];
    float* out = (float*)d_out;

    const int GEMM_SMEM = 96 * 1024;
    cudaFuncSetAttribute(k_gemm128, cudaFuncAttributeMaxDynamicSharedMemorySize, GEMM_SMEM);

    k_setup<<<578, 256>>>(ei, batch,
                          (const float*)d_in[iW[0]], (const float*)d_in[iW[1]],
                          (const float*)d_in[iW[2]], (const float*)d_in[ib[3]],
                          (const float*)d_in[iWlin], (const float*)d_in[iblin]);
    k_hist<<<HB + 64, 256>>>(ei, batch);
    k_scan1<<<SB, 1024>>>();
    k_scan23<<<SB, 1024>>>();
    k_scatter<<<(NE + 255) / 256, 256>>>(ei);

    // layer 1: fused (ÂX)W1 + b1, relu -> split tiles
    k_aggx7<<<NN / 16, 128>>>(x, (const float*)d_in[iW1], (const float*)d_in[ib[0]]);
    // layer 2: MMA + aggregation (emit tiles for layer 3)
    k_gemm128<<<NNP / 64, 256, GEMM_SMEM>>>(0);
    k_aggT<<<NN / 4, 128>>>((const float*)d_in[ib[1]]);
    // layer 3: MMA + aggregation fused with folded layer-4 GEMV
    k_gemm128<<<NNP / 64, 256, GEMM_SMEM>>>(1);
    k_aggG<<<NN / 4, 128>>>((const float*)d_in[ib[2]]);
    // pooled 2-wide aggregation + head
    k_agg2pool<<<(NN + 255) / 256, 256>>>(batch);
    k_out<<<(NGR * 2 + 255) / 256, 256>>>(out);
}

// round 15
// speedup vs baseline: 1.6947x; 1.0702x over previous
#include <cuda_runtime.h>
#include <cuda_bf16.h>
#include <cstdint>

#define NN  100000
#define NNP 100032          // 1563 tiles of 64 rows (pad rows stay zero)
#define NE  1600000
#define NGR 512
#define FIN 7
#define HID 128
#define HB  6250            // edge-hist blocks
#define SB  98              // scan blocks (98*1024 >= NN)

// ---------------- scratch (static device globals; zero-initialized) ----------------
__device__ __align__(16) unsigned d_Hh[(size_t)NNP * 64];   // GEMM out, bf16 pairs, PRESCALED by row dinv
__device__ __align__(16) float d_t [(size_t)NN * 2];        // prescaled by node dinv
// A hi/lo bf16 tiles: [row][256B] XOR-granule swizzled (pad rows stay zero)
__device__ __align__(16) unsigned char d_Ahi[(size_t)NNP * 256];
__device__ __align__(16) unsigned char d_Alo[(size_t)NNP * 256];
// W hi/lo bf16, transposed [n][k], 256B rows, swizzled (32 KB each)
__device__ __align__(16) unsigned char d_B2hi[32768], d_B2lo[32768];
__device__ __align__(16) unsigned char d_B3hi[32768], d_B3lo[32768];
__device__ float d_dinv[NN];
__device__ int   d_counts[NN];
__device__ int   d_cursor[NN];
__device__ int   d_off[NN + 1];
__device__ int   d_bsum[SB];
__device__ int   d_csrc[NE];
__device__ float d_pool2[NGR * 2];
__device__ int   d_gcnt[NGR];
__device__ float d_W4p[HID * 2];
__device__ float d_b4p[2];
__device__ int   d_is64_ei;
__device__ int   d_is64_batch;

__device__ __forceinline__ int load_idx(const void* p, int is64, long long i) {
    return is64 ? (int)((const long long*)p)[i] : ((const int*)p)[i];
}

// ---------------- bf16 helpers (pure value ops — no address-taking) ----------------
__device__ __forceinline__ unsigned short bfh(float v) {
    return __bfloat16_as_ushort(__float2bfloat16(v));
}
__device__ __forceinline__ float bf2f(unsigned short u) {
    return __bfloat162float(__ushort_as_bfloat16(u));
}
// pack two fp32 into bf16x2 (lo in lower 16 bits), register-only asm
__device__ __forceinline__ unsigned packbf2(float lo, float hi) {
    unsigned r;
    asm("cvt.rn.bf16x2.f32 %0, %1, %2;" : "=r"(r) : "f"(hi), "f"(lo));
    return r;
}

// swizzled byte offset within a [rows][256B] bf16 image: 16B granules XORed by row&7
__device__ __forceinline__ unsigned sw_off(int row, int kb) {
    return (unsigned)(row * 256) + ((((unsigned)kb >> 4) ^ ((unsigned)row & 7u)) << 4)
         + ((unsigned)kb & 15u);
}

// ---------------- mma.sync m16n8k16 bf16 ----------------
__device__ __forceinline__ void mma_bf16(float c[4], const unsigned a[4], const unsigned b[2]) {
    asm volatile(
        "mma.sync.aligned.m16n8k16.row.col.f32.bf16.bf16.f32 "
        "{%0,%1,%2,%3}, {%4,%5,%6,%7}, {%8,%9}, {%0,%1,%2,%3};"
        : "+f"(c[0]), "+f"(c[1]), "+f"(c[2]), "+f"(c[3])
        : "r"(a[0]), "r"(a[1]), "r"(a[2]), "r"(a[3]), "r"(b[0]), "r"(b[1]));
}

// ---------------- setup: zero + dtype probe + wconv(W2,W3) + fold ----------------
__global__ void k_setup(const void* ei, const void* batch,
                        const float* __restrict__ W2, const float* __restrict__ W3,
                        const float* __restrict__ W4, const float* __restrict__ b4,
                        const float* __restrict__ Wlin, const float* __restrict__ blin) {
    int bid = blockIdx.x;
    if (bid < 512) {                       // zeroing
        int i = bid * 256 + threadIdx.x;
        int stride = 512 * 256;
        for (int t = i; t < NN; t += stride) { d_counts[t] = 0; d_cursor[t] = 0; }
        for (int t = i; t < NGR * 2; t += stride) d_pool2[t] = 0.f;
        for (int t = i; t < NGR; t += stride) d_gcnt[t] = 0;
    } else if (bid == 512) {               // dtype probe
        if (threadIdx.x < 32) {
            const int* w1 = (const int*)ei;
            const int* w2 = (const int*)batch;
            int lane = threadIdx.x;
            int nz1 = 0, nz2 = 0;
            for (int i = 2 * lane + 1; i < 4096; i += 64) { nz1 |= w1[i]; nz2 |= w2[i]; }
            nz1 = __reduce_or_sync(0xffffffffu, nz1);
            nz2 = __reduce_or_sync(0xffffffffu, nz2);
            if (lane == 0) { d_is64_ei = (nz1 == 0); d_is64_batch = (nz2 == 0); }
        }
    } else if (bid < 577) {                // wconv: split-bf16 transposed W tiles
        int idx64 = bid - 513;             // 0..63
        int sel = idx64 >> 5;
        const float* W = sel ? W3 : W2;
        int idx = (idx64 & 31) * 256 + threadIdx.x;   // < 8192
        int n = idx >> 6;
        int k = (idx & 63) * 2;
        float v0 = W[k * HID + n];
        float v1 = W[(k + 1) * HID + n];
        unsigned short h0 = bfh(v0), h1 = bfh(v1);
        unsigned short l0 = bfh(v0 - bf2f(h0)), l1 = bfh(v1 - bf2f(h1));
        unsigned off = sw_off(n, k * 2);
        unsigned char* bh = sel ? d_B3hi : d_B2hi;
        unsigned char* bl = sel ? d_B3lo : d_B2lo;
        *(unsigned*)(bh + off) = (unsigned)h0 | ((unsigned)h1 << 16);
        *(unsigned*)(bl + off) = (unsigned)l0 | ((unsigned)l1 << 16);
    } else {                               // fold: W4p = W4 @ Wlin, b4p
        int j = threadIdx.x;
        if (j >= HID) return;
        float s0 = 0.f, s1 = 0.f;
#pragma unroll 8
        for (int k = 0; k < HID; k++) {
            float w = W4[j * HID + k];
            s0 += w * Wlin[k * 2 + 0];
            s1 += w * Wlin[k * 2 + 1];
        }
        d_W4p[j * 2 + 0] = s0;
        d_W4p[j * 2 + 1] = s1;
        if (j < 2) {
            float s = 0.f;
            for (int k = 0; k < HID; k++) s += b4[k] * Wlin[k * 2 + j];
            d_b4p[j] = s + blin[j];
        }
    }
}

// ---------------- degree histogram + nodes-per-graph histogram ----------------
__global__ void __launch_bounds__(256) k_hist(const void* __restrict__ ei,
                                              const void* __restrict__ batch) {
    __shared__ int sh[NGR];
    if (blockIdx.x < HB) {
        int e = blockIdx.x * 256 + threadIdx.x;
        if (e >= NE) return;
        unsigned d = (unsigned)load_idx(ei, d_is64_ei, (long long)NE + e);
        if (d < NN) atomicAdd(&d_counts[d], 1);
    } else {
        for (int t = threadIdx.x; t < NGR; t += 256) sh[t] = 0;
        __syncthreads();
        int is64 = d_is64_batch;
        for (int i = (blockIdx.x - HB) * 256 + threadIdx.x; i < NN; i += 64 * 256) {
            unsigned g = (unsigned)load_idx(batch, is64, i);
            if (g < NGR) atomicAdd(&sh[g], 1);
        }
        __syncthreads();
        for (int t = threadIdx.x; t < NGR; t += 256)
            if (sh[t]) atomicAdd(&d_gcnt[t], sh[t]);
    }
}

// ---------------- scan phase 1: per-block reduce (+dinv) ----------------
__global__ void __launch_bounds__(1024) k_scan1() {
    __shared__ int ws[32];
    int i = blockIdx.x * 1024 + threadIdx.x;
    int v = 0;
    if (i < NN) {
        v = d_counts[i];
        d_dinv[i] = rsqrtf((float)v + 1.0f);
    }
    int s = v;
#pragma unroll
    for (int o = 16; o > 0; o >>= 1) s += __shfl_down_sync(0xffffffffu, s, o);
    if ((threadIdx.x & 31) == 0) ws[threadIdx.x >> 5] = s;
    __syncthreads();
    if (threadIdx.x < 32) {
        int t = ws[threadIdx.x];
#pragma unroll
        for (int o = 16; o > 0; o >>= 1) t += __shfl_down_sync(0xffffffffu, t, o);
        if (threadIdx.x == 0) d_bsum[blockIdx.x] = t;
    }
}

// ---------------- scan phases 2+3: base from partials + block scan -> d_off -------
__global__ void __launch_bounds__(1024) k_scan23() {
    __shared__ int sc[32];
    __shared__ int wsum[32];
    __shared__ int sbase;
    int t = threadIdx.x;
    if (t == 0) {
        int base = 0, tot = 0;
        for (int b = 0; b < SB; b++) {
            int v = d_bsum[b];
            if (b < (int)blockIdx.x) base += v;
            tot += v;
        }
        sbase = base;
        if (blockIdx.x == 0) d_off[NN] = tot;
    }
    int i = blockIdx.x * 1024 + t;
    int v = (i < NN) ? d_counts[i] : 0;
    int incl = v;
#pragma unroll
    for (int o = 1; o < 32; o <<= 1) {
        int n = __shfl_up_sync(0xffffffffu, incl, o);
        if ((t & 31) >= o) incl += n;
    }
    if ((t & 31) == 31) wsum[t >> 5] = incl;
    __syncthreads();
    if (t < 32) {
        int w = wsum[t];
#pragma unroll
        for (int o = 1; o < 32; o <<= 1) {
            int n = __shfl_up_sync(0xffffffffu, w, o);
            if (t >= o) w += n;
        }
        sc[t] = w;
    }
    __syncthreads();
    int warp = t >> 5;
    int base = sbase + (warp ? sc[warp - 1] : 0);
    if (i < NN) d_off[i] = base + incl - v;
}

// ---------------- scatter edges into CSR (by dst); norm factored out ----------------
__global__ void k_scatter(const void* __restrict__ ei) {
    int e = blockIdx.x * blockDim.x + threadIdx.x;
    if (e >= NE) return;
    int is64 = d_is64_ei;
    unsigned s = (unsigned)load_idx(ei, is64, e);
    unsigned d = (unsigned)load_idx(ei, is64, (long long)NE + e);
    if (s >= NN || d >= NN) return;
    int pos = d_off[d] + atomicAdd(&d_cursor[d], 1);
    d_csrc[pos] = (int)s;
}

// ---------------- fused: (ÂX)W1 + b1, relu -> split-bf16 A tiles ----------------
__global__ void __launch_bounds__(128) k_aggx7(const float* __restrict__ x,
                                               const float* __restrict__ W1,
                                               const float* __restrict__ b1) {
    __shared__ float sax[16][8];
    __shared__ float sW[FIN * HID];
    __shared__ float sb[HID];
    const int tid = threadIdx.x;
    for (int t = tid; t < FIN * HID; t += 128) sW[t] = W1[t];
    sb[tid] = b1[tid];

    const int sub = tid & 7;
    const int local = tid >> 3;
    const int i = blockIdx.x * 16 + local;          // always < NN
    const int col = (sub < 7) ? sub : 6;
    const float di = d_dinv[i];
    float acc = di * x[i * 7 + col];
    int e = d_off[i];
    const int e1 = d_off[i + 1];
    for (; e + 2 <= e1; e += 2) {
        int s0 = d_csrc[e], s1 = d_csrc[e + 1];
        float w0 = d_dinv[s0], w1 = d_dinv[s1];
        acc += w0 * x[s0 * 7 + col] + w1 * x[s1 * 7 + col];
    }
    if (e < e1) { int s = d_csrc[e]; acc += d_dinv[s] * x[s * 7 + col]; }
    sax[local][sub] = acc * di;
    __syncthreads();

#pragma unroll
    for (int j = 0; j < 8; j++) {
        int task = tid + j * 128;
        int node = task >> 6;
        int jp = (task & 63) * 2;
        float a0 = sb[jp], a1 = sb[jp + 1];
#pragma unroll
        for (int k = 0; k < FIN; k++) {
            float a = sax[node][k];
            a0 += a * sW[k * HID + jp];
            a1 += a * sW[k * HID + jp + 1];
        }
        a0 = fmaxf(a0, 0.f); a1 = fmaxf(a1, 0.f);
        unsigned short h0 = bfh(a0), h1 = bfh(a1);
        unsigned short l0 = bfh(a0 - bf2f(h0)), l1 = bfh(a1 - bf2f(h1));
        int row = blockIdx.x * 16 + node;
        unsigned off = sw_off(row, jp * 2);
        *(unsigned*)(d_Ahi + off) = (unsigned)h0 | ((unsigned)h1 << 16);
        *(unsigned*)(d_Alo + off) = (unsigned)l0 | ((unsigned)l1 << 16);
    }
}

// ---------------- 128x128 GEMM via mma.sync bf16x3 -> d_Hh (bf16, row-prescaled) ---
// 256 threads, 64 rows x 128 cols/block, 1563 CTAs.
__global__ void __launch_bounds__(256) k_gemm128(int sel) {
    extern __shared__ __align__(16) unsigned char smem[];
    unsigned char* As_hi = smem;            // 64*256 = 16 KB
    unsigned char* As_lo = smem + 16384;
    unsigned char* Bs_hi = smem + 32768;    // 128*256 = 32 KB
    unsigned char* Bs_lo = smem + 65536;
    const int tid = threadIdx.x;

    {
        const uint4* ah = (const uint4*)d_Ahi + (size_t)blockIdx.x * 1024;
        const uint4* al = (const uint4*)d_Alo + (size_t)blockIdx.x * 1024;
        const uint4* bh = (const uint4*)(sel ? d_B3hi : d_B2hi);
        const uint4* bl = (const uint4*)(sel ? d_B3lo : d_B2lo);
        uint4* sah = (uint4*)As_hi;
        uint4* sal = (uint4*)As_lo;
        uint4* sbh = (uint4*)Bs_hi;
        uint4* sbl = (uint4*)Bs_lo;
#pragma unroll
        for (int i = 0; i < 4; i++) sah[tid + i * 256] = ah[tid + i * 256];
#pragma unroll
        for (int i = 0; i < 4; i++) sal[tid + i * 256] = al[tid + i * 256];
#pragma unroll
        for (int i = 0; i < 8; i++) sbh[tid + i * 256] = bh[tid + i * 256];
#pragma unroll
        for (int i = 0; i < 8; i++) sbl[tid + i * 256] = bl[tid + i * 256];
    }
    __syncthreads();

    const int w = tid >> 5, lane = tid & 31;
    const int wm = (w & 1) * 32;
    const int wn = (w >> 1) * 32;
    const int lr = lane >> 2;
    const int kq = (lane & 3) * 4;

    float c[2][4][4] = {};

#pragma unroll
    for (int ks = 0; ks < 8; ks++) {
        const int kb0 = ks * 32;
        unsigned ah[2][4], al[2][4], bh[4][2], bl[4][2];
#pragma unroll
        for (int mt = 0; mt < 2; mt++) {
            int r = wm + mt * 16 + lr;
            ah[mt][0] = *(const unsigned*)(As_hi + sw_off(r,     kb0 + kq));
            ah[mt][1] = *(const unsigned*)(As_hi + sw_off(r + 8, kb0 + kq));
            ah[mt][2] = *(const unsigned*)(As_hi + sw_off(r,     kb0 + 16 + kq));
            ah[mt][3] = *(const unsigned*)(As_hi + sw_off(r + 8, kb0 + 16 + kq));
            al[mt][0] = *(const unsigned*)(As_lo + sw_off(r,     kb0 + kq));
            al[mt][1] = *(const unsigned*)(As_lo + sw_off(r + 8, kb0 + kq));
            al[mt][2] = *(const unsigned*)(As_lo + sw_off(r,     kb0 + 16 + kq));
            al[mt][3] = *(const unsigned*)(As_lo + sw_off(r + 8, kb0 + 16 + kq));
        }
#pragma unroll
        for (int nt = 0; nt < 4; nt++) {
            int n = wn + nt * 8 + lr;
            bh[nt][0] = *(const unsigned*)(Bs_hi + sw_off(n, kb0 + kq));
            bh[nt][1] = *(const unsigned*)(Bs_hi + sw_off(n, kb0 + 16 + kq));
            bl[nt][0] = *(const unsigned*)(Bs_lo + sw_off(n, kb0 + kq));
            bl[nt][1] = *(const unsigned*)(Bs_lo + sw_off(n, kb0 + 16 + kq));
        }
#pragma unroll
        for (int mt = 0; mt < 2; mt++)
#pragma unroll
            for (int nt = 0; nt < 4; nt++) {
                mma_bf16(c[mt][nt], ah[mt], bh[nt]);
                mma_bf16(c[mt][nt], ah[mt], bl[nt]);
                mma_bf16(c[mt][nt], al[mt], bh[nt]);
            }
    }

    // epilogue: prescale each row by its own dinv, pack bf16x2 -> d_Hh
    const int node0 = blockIdx.x * 64;
#pragma unroll
    for (int mt = 0; mt < 2; mt++) {
        int row = node0 + wm + mt * 16 + lr;
        float dr0 = (row     < NN) ? d_dinv[row]     : 0.f;
        float dr8 = (row + 8 < NN) ? d_dinv[row + 8] : 0.f;
#pragma unroll
        for (int nt = 0; nt < 4; nt++) {
            int cu = (wn + nt * 8 + (lane & 3) * 2) >> 1;
            d_Hh[(size_t)row * 64 + cu]       = packbf2(c[mt][nt][0] * dr0, c[mt][nt][1] * dr0);
            d_Hh[(size_t)(row + 8) * 64 + cu] = packbf2(c[mt][nt][2] * dr8, c[mt][nt][3] * dr8);
        }
    }
}

// ---------------- aggregation core: rows prescaled -> pure gather-sum --------------
// returns di * (v'_i + sum v'_s) + b  where v'_r = dinv_r * v_r (stored in d_Hh)
__device__ __forceinline__ float4 agg_core(int i, int lane, const float* __restrict__ b) {
    const uint2* hw2 = (const uint2*)d_Hh;
    const float di = d_dinv[i];
    uint2 rs = hw2[(size_t)i * 32 + lane];
    float4 acc;
    acc.x = __uint_as_float(rs.x << 16);
    acc.y = __uint_as_float(rs.x & 0xffff0000u);
    acc.z = __uint_as_float(rs.y << 16);
    acc.w = __uint_as_float(rs.y & 0xffff0000u);
    int e = d_off[i];
    const int e1 = d_off[i + 1];
    for (; e + 8 <= e1; e += 8) {
        int s[8]; uint2 r[8];
#pragma unroll
        for (int j = 0; j < 8; j++) s[j] = d_csrc[e + j];
#pragma unroll
        for (int j = 0; j < 8; j++) r[j] = hw2[(size_t)s[j] * 32 + lane];
#pragma unroll
        for (int j = 0; j < 8; j++) {
            acc.x += __uint_as_float(r[j].x << 16);
            acc.y += __uint_as_float(r[j].x & 0xffff0000u);
            acc.z += __uint_as_float(r[j].y << 16);
            acc.w += __uint_as_float(r[j].y & 0xffff0000u);
        }
    }
    for (; e < e1; e++) {
        int sIdx = d_csrc[e];
        uint2 r = hw2[(size_t)sIdx * 32 + lane];
        acc.x += __uint_as_float(r.x << 16);
        acc.y += __uint_as_float(r.x & 0xffff0000u);
        acc.z += __uint_as_float(r.y << 16);
        acc.w += __uint_as_float(r.y & 0xffff0000u);
    }
    float4 bv = ((const float4*)b)[lane];
    acc.x = acc.x * di + bv.x; acc.y = acc.y * di + bv.y;
    acc.z = acc.z * di + bv.z; acc.w = acc.w * di + bv.w;
    return acc;
}

// layer-2 aggregation: emit relu'd split-bf16 A tiles for the next GEMM
__global__ void __launch_bounds__(128) k_aggT(const float* __restrict__ b) {
    const int lane = threadIdx.x & 31;
    const int i = blockIdx.x * 4 + (threadIdx.x >> 5);
    if (i >= NN) return;
    float4 acc = agg_core(i, lane, b);
    acc.x = fmaxf(acc.x, 0.f); acc.y = fmaxf(acc.y, 0.f);
    acc.z = fmaxf(acc.z, 0.f); acc.w = fmaxf(acc.w, 0.f);
    unsigned short h0 = bfh(acc.x), h1 = bfh(acc.y), h2 = bfh(acc.z), h3 = bfh(acc.w);
    unsigned short l0 = bfh(acc.x - bf2f(h0)), l1 = bfh(acc.y - bf2f(h1));
    unsigned short l2 = bfh(acc.z - bf2f(h2)), l3 = bfh(acc.w - bf2f(h3));
    unsigned long long ph = (unsigned long long)((unsigned)h0 | ((unsigned)h1 << 16))
                          | ((unsigned long long)((unsigned)h2 | ((unsigned)h3 << 16)) << 32);
    unsigned long long pl = (unsigned long long)((unsigned)l0 | ((unsigned)l1 << 16))
                          | ((unsigned long long)((unsigned)l2 | ((unsigned)l3 << 16)) << 32);
    unsigned off = sw_off(i, lane * 8);
    *(unsigned long long*)(d_Ahi + off) = ph;
    *(unsigned long long*)(d_Alo + off) = pl;
}

// layer-3 aggregation fused with folded layer-4 GEMV: d_t = dinv_i * (relu(agg) @ W4p)
__global__ void __launch_bounds__(128) k_aggG(const float* __restrict__ b) {
    __shared__ float sw[HID * 2];
    const int tid = threadIdx.x;
    sw[tid] = d_W4p[tid];
    sw[tid + 128] = d_W4p[tid + 128];
    __syncthreads();

    const int lane = tid & 31;
    const int i = blockIdx.x * 4 + (tid >> 5);
    if (i >= NN) return;
    float4 a = agg_core(i, lane, b);
    a.x = fmaxf(a.x, 0.f); a.y = fmaxf(a.y, 0.f);
    a.z = fmaxf(a.z, 0.f); a.w = fmaxf(a.w, 0.f);
    const int j0 = lane * 4;
    float s0 = a.x * sw[(j0+0)*2]   + a.y * sw[(j0+1)*2]   + a.z * sw[(j0+2)*2]   + a.w * sw[(j0+3)*2];
    float s1 = a.x * sw[(j0+0)*2+1] + a.y * sw[(j0+1)*2+1] + a.z * sw[(j0+2)*2+1] + a.w * sw[(j0+3)*2+1];
#pragma unroll
    for (int o = 16; o > 0; o >>= 1) {
        s0 += __shfl_down_sync(0xffffffffu, s0, o);
        s1 += __shfl_down_sync(0xffffffffu, s1, o);
    }
    if (lane == 0) {
        float di = d_dinv[i];           // prescale for the pooling aggregation
        d_t[i * 2 + 0] = s0 * di;
        d_t[i * 2 + 1] = s1 * di;
    }
}

// ---------------- 2-wide aggregation fused with pooling (warp-agg atomics) ---------
// d_t rows are prescaled: out_i = di * (t'_i + sum t'_s)
__global__ void k_agg2pool(const void* __restrict__ batch) {
    int i = blockIdx.x * blockDim.x + threadIdx.x;
    bool valid = i < NN;
    float a0 = 0.f, a1 = 0.f;
    unsigned g = 0xffffffffu;
    if (valid) {
        const float2* t2 = (const float2*)d_t;
        const float di = d_dinv[i];
        float2 ti = t2[i];
        a0 = ti.x; a1 = ti.y;
        const int e1 = d_off[i + 1];
        for (int e = d_off[i]; e < e1; e++) {
            int s = d_csrc[e];
            float2 ts = t2[s];
            a0 += ts.x; a1 += ts.y;
        }
        a0 *= di; a1 *= di;
        g = (unsigned)load_idx(batch, d_is64_batch, i);
    }
    unsigned g0 = __shfl_sync(0xffffffffu, g, 0);
    bool uni = __all_sync(0xffffffffu, g == g0);
    if (uni && g0 < NGR) {
#pragma unroll
        for (int o = 16; o > 0; o >>= 1) {
            a0 += __shfl_down_sync(0xffffffffu, a0, o);
            a1 += __shfl_down_sync(0xffffffffu, a1, o);
        }
        if ((threadIdx.x & 31) == 0) {
            atomicAdd(&d_pool2[g0 * 2 + 0], a0);
            atomicAdd(&d_pool2[g0 * 2 + 1], a1);
        }
    } else if (valid && g < NGR) {
        atomicAdd(&d_pool2[g * 2 + 0], a0);
        atomicAdd(&d_pool2[g * 2 + 1], a1);
    }
}

// ---------------- output: mean + folded bias ----------------
__global__ void k_out(float* __restrict__ out) {
    int idx = blockIdx.x * blockDim.x + threadIdx.x;
    if (idx >= NGR * 2) return;
    int g = idx >> 1, c = idx & 1;
    float cnt = fmaxf((float)d_gcnt[g], 1.0f);
    out[idx] = d_pool2[g * 2 + c] / cnt + d_b4p[c];
}

// ---------------- launch ----------------
extern "C" void kernel_launch(void* const* d_in, const int* in_sizes, int n_in,
                              void* d_out, int out_size) {
    // Resolve inputs by element count — robust to metadata ordering.
    int ix = 0, iei = 1, ibatch = 2, iW1 = 3, iWlin = 11, iblin = 12;
    int iW[3] = {5, 7, 9};
    int ib[4] = {4, 6, 8, 10};
    {
        int nW = 0, nb = 0;
        int fx = -1, fei = -1, fb = -1, fW1 = -1, fWl = -1, fbl = -1;
        int fW[3] = {-1, -1, -1}, fbias[4] = {-1, -1, -1, -1};
        for (int i = 0; i < n_in; i++) {
            switch (in_sizes[i]) {
                case 700000:  fx  = i; break;
                case 3200000: fei = i; break;
                case 100000:  fb  = i; break;
                case 896:     fW1 = i; break;
                case 16384:   if (nW < 3) fW[nW++] = i; break;
                case 128:     if (nb < 4) fbias[nb++] = i; break;
                case 256:     fWl = i; break;
                case 2:       fbl = i; break;
                default: break;
            }
        }
        if (fx >= 0 && fei >= 0 && fb >= 0 && fW1 >= 0 && fWl >= 0 && fbl >= 0 &&
            nW == 3 && nb == 4) {
            ix = fx; iei = fei; ibatch = fb; iW1 = fW1; iWlin = fWl; iblin = fbl;
            iW[0] = fW[0]; iW[1] = fW[1]; iW[2] = fW[2];
            ib[0] = fbias[0]; ib[1] = fbias[1]; ib[2] = fbias[2]; ib[3] = fbias[3];
        }
    }

    const float* x     = (const float*)d_in[ix];
    const void*  ei    = d_in[iei];
    const void*  batch = d_in[ibatch];
    float* out = (float*)d_out;

    const int GEMM_SMEM = 96 * 1024;
    cudaFuncSetAttribute(k_gemm128, cudaFuncAttributeMaxDynamicSharedMemorySize, GEMM_SMEM);

    k_setup<<<578, 256>>>(ei, batch,
                          (const float*)d_in[iW[0]], (const float*)d_in[iW[1]],
                          (const float*)d_in[iW[2]], (const float*)d_in[ib[3]],
                          (const float*)d_in[iWlin], (const float*)d_in[iblin]);
    k_hist<<<HB + 64, 256>>>(ei, batch);
    k_scan1<<<SB, 1024>>>();
    k_scan23<<<SB, 1024>>>();
    k_scatter<<<(NE + 255) / 256, 256>>>(ei);

    // layer 1: fused (ÂX)W1 + b1, relu -> split tiles
    k_aggx7<<<NN / 16, 128>>>(x, (const float*)d_in[iW1], (const float*)d_in[ib[0]]);
    // layer 2: MMA (epilogue prescales rows by dinv) + gather-sum aggregation
    k_gemm128<<<NNP / 64, 256, GEMM_SMEM>>>(0);
    k_aggT<<<NN / 4, 128>>>((const float*)d_in[ib[1]]);
    // layer 3: MMA + aggregation fused with folded layer-4 GEMV (output prescaled)
    k_gemm128<<<NNP / 64, 256, GEMM_SMEM>>>(1);
    k_aggG<<<NN / 4, 128>>>((const float*)d_in[ib[2]]);
    // pooled 2-wide aggregation + head
    k_agg2pool<<<(NN + 255) / 256, 256>>>(batch);
    k_out<<<(NGR * 2 + 255) / 256, 256>>>(out);
}